// round 2
// baseline (speedup 1.0000x reference)
#include <cuda_runtime.h>
#include <cstdint>

// Problem-shape upper bounds (this problem: N=100000, E=1600000, E+N=1700000)
#define MAXN 100000
#define MAXE 1700000

// ---------------- device scratch (static, allocation-free) ----------------
__device__ float g_h1[(size_t)MAXN * 64];      // layer-1 transformed features
__device__ float g_out1[(size_t)MAXN * 64];    // layer-1 aggregated output
__device__ float g_as1[MAXN];                  // per-node a_src (layer 1)
__device__ float g_ad1[MAXN];                  // per-node a_dst (layer 1)
__device__ float4 g_node2[MAXN];               // {h3_0, h3_1, a_src2, a_dst2}
__device__ int2  g_sedge[MAXE];                // dst-sorted {src, raw_edge_attr_bits}
__device__ int   g_deg[MAXN];
__device__ int   g_start[MAXN + 1];
__device__ int   g_cursor[MAXN];
__device__ float g_sum_ea;
__device__ float g_scal[6];                    // {c1, -, c2, -, mean_ea, -}

// ---------------- zero-init (tiny: histogram counters + reduction cell) ----------------
__global__ void zero_kernel(int N) {
    int i = blockIdx.x * blockDim.x + threadIdx.x;
    if (i < N) g_deg[i] = 0;
    if (i == 0) g_sum_ea = 0.f;
}

// ---------------- mean(edge_attr) reduction ----------------
__global__ void sum_ea_kernel(const float* __restrict__ ea, int n) {
    __shared__ float sdata[8];
    float s = 0.f;
    for (int i = blockIdx.x * blockDim.x + threadIdx.x; i < n; i += gridDim.x * blockDim.x)
        s += ea[i];
    #pragma unroll
    for (int o = 16; o; o >>= 1) s += __shfl_xor_sync(0xffffffffu, s, o);
    if ((threadIdx.x & 31) == 0) sdata[threadIdx.x >> 5] = s;
    __syncthreads();
    if (threadIdx.x < 8) {
        float v = sdata[threadIdx.x];
        #pragma unroll
        for (int o = 4; o; o >>= 1) v += __shfl_xor_sync(0xffu, v, o);
        if (threadIdx.x == 0) atomicAdd(&g_sum_ea, v);
    }
}

// ---------------- scalar edge constants ----------------
__global__ void scalars_kernel(const float* __restrict__ We1, const float* __restrict__ ae1,
                               const float* __restrict__ We2, const float* __restrict__ ae2,
                               int H, int C, float invE) {
    if (threadIdx.x == 0) {
        float c1 = 0.f;
        for (int k = 0; k < H; k++) c1 += We1[k] * ae1[k];
        float c2 = 0.f;
        for (int k = 0; k < C; k++) c2 += We2[k] * ae2[k];
        g_scal[0] = c1;
        g_scal[2] = c2;
        g_scal[4] = g_sum_ea * invE;   // mean edge attr (self-loop fill value)
    }
}

// ---------------- histogram of destination degrees ----------------
__global__ void hist_kernel(const int* __restrict__ ei, int E, int N) {
    int t = blockIdx.x * blockDim.x + threadIdx.x;
    if (t >= E + N) return;
    int d = (t < E) ? ei[E + t] : (t - E);
    atomicAdd(&g_deg[d], 1);
}

// ---------------- single-block exclusive scan over degrees ----------------
__global__ void __launch_bounds__(1024) scan_kernel(int N) {
    __shared__ int sh[1024];
    const int tid = threadIdx.x;
    const int chunk = (N + 1023) / 1024;
    const int b = tid * chunk;
    const int e = min(b + chunk, N);
    int s = 0;
    for (int i = b; i < e; i++) s += g_deg[i];
    sh[tid] = s;
    __syncthreads();
    #pragma unroll
    for (int off = 1; off < 1024; off <<= 1) {
        int v = (tid >= off) ? sh[tid - off] : 0;
        __syncthreads();
        sh[tid] += v;
        __syncthreads();
    }
    int run = (tid > 0) ? sh[tid - 1] : 0;
    for (int i = b; i < e; i++) {
        g_start[i] = run;
        g_cursor[i] = run;
        run += g_deg[i];
    }
    if (e == N && b <= N) g_start[N] = run;
}

// ---------------- scatter edges into dst-sorted order ----------------
__global__ void sort_kernel(const int* __restrict__ ei, const float* __restrict__ ea,
                            int E, int N) {
    int t = blockIdx.x * blockDim.x + threadIdx.x;
    if (t >= E + N) return;
    int s, d; float u;
    if (t < E) { s = ei[t]; d = ei[E + t]; u = ea[t]; }
    else       { s = d = t - E; u = g_scal[4]; }
    int pos = atomicAdd(&g_cursor[d], 1);
    g_sedge[pos] = make_int2(s, __float_as_int(u));
}

// ---------------- SGEMM: h1 = x[M,128] @ W1[128,64] ----------------
// 256 threads, tile 128(M) x 64(N), 8x4 per thread, K-chunks of 16.
__global__ void __launch_bounds__(256) gemm1_kernel(const float* __restrict__ x,
                                                    const float* __restrict__ W, int M) {
    __shared__ float Xs[16][128];
    __shared__ float Ws[16][64];
    const int tid = threadIdx.x;
    const int tr = tid >> 4;        // 0..15 -> 8 rows each
    const int tc = tid & 15;        // 0..15 -> 4 cols each
    const int m0 = blockIdx.x * 128;
    float acc[8][4];
    #pragma unroll
    for (int i = 0; i < 8; i++)
        #pragma unroll
        for (int j = 0; j < 4; j++) acc[i][j] = 0.f;

    for (int k0 = 0; k0 < 128; k0 += 16) {
        // stage X tile: 128 rows x 16 k = 512 float4, 256 threads -> 2 iters
        #pragma unroll
        for (int it = 0; it < 2; it++) {
            int f = it * 256 + tid;           // 0..511
            int row = f >> 2;
            int kq = (f & 3) * 4;
            float4 v = make_float4(0.f, 0.f, 0.f, 0.f);
            int gr = m0 + row;
            if (gr < M) v = *(const float4*)&x[(size_t)gr * 128 + k0 + kq];
            Xs[kq + 0][row] = v.x; Xs[kq + 1][row] = v.y;
            Xs[kq + 2][row] = v.z; Xs[kq + 3][row] = v.w;
        }
        // stage W tile: 16 k x 64 cols = 256 float4 -> 1 iter
        {
            int kk = tid >> 4;
            int c4 = (tid & 15) * 4;
            *(float4*)&Ws[kk][c4] = *(const float4*)&W[(size_t)(k0 + kk) * 64 + c4];
        }
        __syncthreads();
        #pragma unroll
        for (int kk = 0; kk < 16; kk++) {
            float a[8], b[4];
            *(float4*)&a[0] = *(float4*)&Xs[kk][tr * 8];
            *(float4*)&a[4] = *(float4*)&Xs[kk][tr * 8 + 4];
            *(float4*)&b[0] = *(float4*)&Ws[kk][tc * 4];
            #pragma unroll
            for (int i = 0; i < 8; i++)
                #pragma unroll
                for (int j = 0; j < 4; j++) acc[i][j] += a[i] * b[j];
        }
        __syncthreads();
    }
    #pragma unroll
    for (int i = 0; i < 8; i++) {
        int gr = m0 + tr * 8 + i;
        if (gr < M) {
            float4 v = make_float4(acc[i][0], acc[i][1], acc[i][2], acc[i][3]);
            *(float4*)&g_h1[(size_t)gr * 64 + tc * 4] = v;
        }
    }
}

// ---------------- per-node attention logit contributions (layer 1) ----------------
__global__ void asd_kernel(const float* __restrict__ att_s, const float* __restrict__ att_d, int N) {
    int warp = (blockIdx.x * blockDim.x + threadIdx.x) >> 5;
    int lane = threadIdx.x & 31;
    if (warp >= N) return;
    float2 v = *(const float2*)&g_h1[(size_t)warp * 64 + lane * 2];
    float as = v.x * att_s[2 * lane] + v.y * att_s[2 * lane + 1];
    float ad = v.x * att_d[2 * lane] + v.y * att_d[2 * lane + 1];
    #pragma unroll
    for (int o = 16; o; o >>= 1) {
        as += __shfl_xor_sync(0xffffffffu, as, o);
        ad += __shfl_xor_sync(0xffffffffu, ad, o);
    }
    if (lane == 0) { g_as1[warp] = as; g_ad1[warp] = ad; }
}

// ---------------- layer-1 aggregation: warp per dst node, register accumulation -------
__global__ void aggr1_kernel(int N) {
    int warp = (blockIdx.x * blockDim.x + threadIdx.x) >> 5;
    int lane = threadIdx.x & 31;
    if (warp >= N) return;
    const float c1 = g_scal[0];
    const float add = g_ad1[warp];
    const int beg = g_start[warp];
    const int end = g_start[warp + 1];
    float2 acc = make_float2(0.f, 0.f);
    float dsum = 0.f;
    for (int i = beg; i < end; i++) {
        int2 se = g_sedge[i];                      // broadcast load
        float as = g_as1[se.x];                    // broadcast gather
        float lg = as + add + __int_as_float(se.y) * c1;
        lg = lg > 0.f ? lg : 0.2f * lg;
        float w = __expf(lg);
        float2 hv = *(const float2*)&g_h1[(size_t)se.x * 64 + 2 * lane];
        acc.x += w * hv.x;
        acc.y += w * hv.y;
        dsum += w;
    }
    float inv = 1.f / (dsum + 1e-16f);
    float2 o = make_float2(acc.x * inv, acc.y * inv);
    *(float2*)&g_out1[(size_t)warp * 64 + 2 * lane] = o;
}

// ---------------- mid: bias+relu, h3 = h2 @ W2[64,2], pack node2 ----------------
__global__ void mid_kernel(const float* __restrict__ W2, const float* __restrict__ bias1,
                           const float* __restrict__ as2, const float* __restrict__ ad2, int N) {
    int warp = (blockIdx.x * blockDim.x + threadIdx.x) >> 5;
    int lane = threadIdx.x & 31;
    if (warp >= N) return;
    float2 v = *(const float2*)&g_out1[(size_t)warp * 64 + lane * 2];
    float2 b = *(const float2*)&bias1[lane * 2];
    float v0 = fmaxf(v.x + b.x, 0.f);
    float v1 = fmaxf(v.y + b.y, 0.f);
    float4 w = *(const float4*)&W2[lane * 4];   // rows 2*lane, 2*lane+1 of [64,2]
    float s0 = v0 * w.x + v1 * w.z;
    float s1 = v0 * w.y + v1 * w.w;
    #pragma unroll
    for (int o = 16; o; o >>= 1) {
        s0 += __shfl_xor_sync(0xffffffffu, s0, o);
        s1 += __shfl_xor_sync(0xffffffffu, s1, o);
    }
    if (lane == 0) {
        g_node2[warp] = make_float4(s0, s1,
                                    s0 * as2[0] + s1 * as2[1],
                                    s0 * ad2[0] + s1 * ad2[1]);
    }
}

// ---------------- layer-2 aggregation + bias + log_softmax (thread per node) ----------
__global__ void aggr2_kernel(const float* __restrict__ bias2, float* __restrict__ out, int N) {
    int i = blockIdx.x * blockDim.x + threadIdx.x;
    if (i >= N) return;
    const float c2 = g_scal[2];
    const float add = g_node2[i].w;
    const int beg = g_start[i];
    const int end = g_start[i + 1];
    float a0 = 0.f, a1 = 0.f, dsum = 0.f;
    for (int j = beg; j < end; j++) {
        int2 se = g_sedge[j];
        float4 ns = g_node2[se.x];
        float lg = ns.z + add + __int_as_float(se.y) * c2;
        lg = lg > 0.f ? lg : 0.2f * lg;
        float w = __expf(lg);
        a0 += w * ns.x;
        a1 += w * ns.y;
        dsum += w;
    }
    float inv = 1.f / (dsum + 1e-16f);
    float o0 = a0 * inv + bias2[0];
    float o1 = a1 * inv + bias2[1];
    float m = fmaxf(o0, o1);
    float z = logf(expf(o0 - m) + expf(o1 - m));
    out[2 * i] = o0 - m - z;
    out[2 * i + 1] = o1 - m - z;
}

// ---------------- host launcher ----------------
extern "C" void kernel_launch(void* const* d_in, const int* in_sizes, int n_in,
                              void* d_out, int out_size) {
    const float* x   = (const float*)d_in[0];
    const int*   ei  = (const int*)d_in[1];
    const float* ea  = (const float*)d_in[2];
    const float* W1  = (const float*)d_in[3];
    const float* as1 = (const float*)d_in[4];
    const float* ad1 = (const float*)d_in[5];
    const float* We1 = (const float*)d_in[6];
    const float* ae1 = (const float*)d_in[7];
    const float* b1  = (const float*)d_in[8];
    const float* W2  = (const float*)d_in[9];
    const float* as2 = (const float*)d_in[10];
    const float* ad2 = (const float*)d_in[11];
    const float* We2 = (const float*)d_in[12];
    const float* ae2 = (const float*)d_in[13];
    const float* b2  = (const float*)d_in[14];
    float* out = (float*)d_out;

    const int H   = in_sizes[4];          // 64
    const int Fin = in_sizes[3] / H;      // 128
    const int N   = in_sizes[0] / Fin;    // 100000
    const int E   = in_sizes[1] / 2;      // 1600000
    const int C   = in_sizes[10];         // 2
    const int nea = in_sizes[2];          // E * ED

    const int T = 256;

    zero_kernel<<<(N + T - 1) / T, T>>>(N);
    sum_ea_kernel<<<512, T>>>(ea, nea);
    scalars_kernel<<<1, 32>>>(We1, ae1, We2, ae2, H, C, 1.0f / (float)E);

    hist_kernel<<<(E + N + T - 1) / T, T>>>(ei, E, N);
    scan_kernel<<<1, 1024>>>(N);
    sort_kernel<<<(E + N + T - 1) / T, T>>>(ei, ea, E, N);

    gemm1_kernel<<<(N + 127) / 128, 256>>>(x, W1, N);
    asd_kernel<<<(N * 32 + T - 1) / T, T>>>(as1, ad1, N);

    aggr1_kernel<<<(N * 32 + T - 1) / T, T>>>(N);

    mid_kernel<<<(N * 32 + T - 1) / T, T>>>(W2, b1, as2, ad2, N);

    aggr2_kernel<<<(N + T - 1) / T, T>>>(b2, out, N);
}

// round 3
// speedup vs baseline: 1.5279x; 1.5279x over previous
#include <cuda_runtime.h>
#include <cstdint>

// Problem-shape upper bounds (this problem: N=100000, E=1600000, E+N=1700000)
#define MAXN 100000
#define MAXE 1700000

// ---------------- device scratch (static, allocation-free) ----------------
__device__ float g_h1[(size_t)MAXN * 64];      // layer-1 transformed features
__device__ float g_as1[MAXN];                  // per-node a_src (layer 1)
__device__ float g_ad1[MAXN];                  // per-node a_dst (layer 1)
__device__ float4 g_node2[MAXN];               // {h3_0, h3_1, a_src2, a_dst2}
__device__ int2  g_sedge[MAXE];                // dst-sorted {src, w1_bits}
__device__ float g_sattr[MAXE];                // dst-sorted raw edge attr
__device__ int   g_deg[MAXN];
__device__ int   g_start[MAXN + 1];
__device__ int   g_cursor[MAXN];
__device__ float g_sum_ea;
__device__ float g_scal[6];                    // {c1, -, c2, -, mean_ea, -}

// ---------------- zero-init ----------------
__global__ void zero_kernel(int N) {
    int i = blockIdx.x * blockDim.x + threadIdx.x;
    if (i < N) g_deg[i] = 0;
    if (i == 0) g_sum_ea = 0.f;
}

// ---------------- mean(edge_attr) reduction ----------------
__global__ void sum_ea_kernel(const float* __restrict__ ea, int n) {
    __shared__ float sdata[8];
    float s = 0.f;
    for (int i = blockIdx.x * blockDim.x + threadIdx.x; i < n; i += gridDim.x * blockDim.x)
        s += ea[i];
    #pragma unroll
    for (int o = 16; o; o >>= 1) s += __shfl_xor_sync(0xffffffffu, s, o);
    if ((threadIdx.x & 31) == 0) sdata[threadIdx.x >> 5] = s;
    __syncthreads();
    if (threadIdx.x < 8) {
        float v = sdata[threadIdx.x];
        #pragma unroll
        for (int o = 4; o; o >>= 1) v += __shfl_xor_sync(0xffu, v, o);
        if (threadIdx.x == 0) atomicAdd(&g_sum_ea, v);
    }
}

// ---------------- scalar edge constants ----------------
__global__ void scalars_kernel(const float* __restrict__ We1, const float* __restrict__ ae1,
                               const float* __restrict__ We2, const float* __restrict__ ae2,
                               int H, int C, float invE) {
    if (threadIdx.x == 0) {
        float c1 = 0.f;
        for (int k = 0; k < H; k++) c1 += We1[k] * ae1[k];
        float c2 = 0.f;
        for (int k = 0; k < C; k++) c2 += We2[k] * ae2[k];
        g_scal[0] = c1;
        g_scal[2] = c2;
        g_scal[4] = g_sum_ea * invE;   // mean edge attr (self-loop fill value)
    }
}

// ---------------- histogram of destination degrees (4 items/thread) ----------------
__global__ void hist_kernel(const int* __restrict__ ei, int E, int N) {
    int t = blockIdx.x * blockDim.x + threadIdx.x;
    int eB = (E + 3) >> 2;
    int nB = (N + 3) >> 2;
    if (t < eB) {
        int q = t * 4;
        if (q + 3 < E && ((E & 3) == 0)) {
            int4 d4 = *(const int4*)&ei[E + q];
            atomicAdd(&g_deg[d4.x], 1);
            atomicAdd(&g_deg[d4.y], 1);
            atomicAdd(&g_deg[d4.z], 1);
            atomicAdd(&g_deg[d4.w], 1);
        } else {
            for (int k = 0; k < 4 && q + k < E; k++)
                atomicAdd(&g_deg[ei[E + q + k]], 1);
        }
    } else if (t < eB + nB) {
        int i0 = (t - eB) * 4;
        for (int k = 0; k < 4 && i0 + k < N; k++)
            atomicAdd(&g_deg[i0 + k], 1);
    }
}

// ---------------- single-block exclusive scan over degrees ----------------
__global__ void __launch_bounds__(1024) scan_kernel(int N) {
    __shared__ int sh[1024];
    const int tid = threadIdx.x;
    const int chunk = (((N + 1023) / 1024) + 3) & ~3;   // multiple of 4
    const int b = tid * chunk;
    const int e = min(b + chunk, N);
    int s = 0;
    if (b < N) {
        int i = b;
        for (; i + 3 < e; i += 4) {
            int4 v = *(const int4*)&g_deg[i];
            s += v.x + v.y + v.z + v.w;
        }
        for (; i < e; i++) s += g_deg[i];
    }
    sh[tid] = s;
    __syncthreads();
    #pragma unroll
    for (int off = 1; off < 1024; off <<= 1) {
        int v = (tid >= off) ? sh[tid - off] : 0;
        __syncthreads();
        sh[tid] += v;
        __syncthreads();
    }
    if (b < N) {
        int run = (tid > 0) ? sh[tid - 1] : 0;
        int i = b;
        for (; i + 3 < e; i += 4) {
            int4 v = *(const int4*)&g_deg[i];
            int4 st = make_int4(run, run + v.x, run + v.x + v.y, run + v.x + v.y + v.z);
            *(int4*)&g_start[i] = st;
            *(int4*)&g_cursor[i] = st;
            run += v.x + v.y + v.z + v.w;
        }
        for (; i < e; i++) {
            g_start[i] = run; g_cursor[i] = run;
            run += g_deg[i];
        }
        if (e == N) g_start[N] = run;
    }
}

// ---------------- SGEMM: h1 = x[M,128] @ W1[128,64], fused a_src/a_dst ----------------
// 256 threads, tile 128(M) x 64(N), 8x4 per thread, K-chunks of 16.
__global__ void __launch_bounds__(256) gemm1_kernel(const float* __restrict__ x,
                                                    const float* __restrict__ W,
                                                    const float* __restrict__ att_s,
                                                    const float* __restrict__ att_d, int M) {
    __shared__ float Xs[16][128];
    __shared__ float Ws[16][64];
    const int tid = threadIdx.x;
    const int tr = tid >> 4;        // 0..15 -> 8 rows each
    const int tc = tid & 15;        // 0..15 -> 4 cols each
    const int m0 = blockIdx.x * 128;
    float acc[8][4];
    #pragma unroll
    for (int i = 0; i < 8; i++)
        #pragma unroll
        for (int j = 0; j < 4; j++) acc[i][j] = 0.f;

    for (int k0 = 0; k0 < 128; k0 += 16) {
        #pragma unroll
        for (int it = 0; it < 2; it++) {
            int f = it * 256 + tid;           // 0..511
            int row = f >> 2;
            int kq = (f & 3) * 4;
            float4 v = make_float4(0.f, 0.f, 0.f, 0.f);
            int gr = m0 + row;
            if (gr < M) v = *(const float4*)&x[(size_t)gr * 128 + k0 + kq];
            Xs[kq + 0][row] = v.x; Xs[kq + 1][row] = v.y;
            Xs[kq + 2][row] = v.z; Xs[kq + 3][row] = v.w;
        }
        {
            int kk = tid >> 4;
            int c4 = (tid & 15) * 4;
            *(float4*)&Ws[kk][c4] = *(const float4*)&W[(size_t)(k0 + kk) * 64 + c4];
        }
        __syncthreads();
        #pragma unroll
        for (int kk = 0; kk < 16; kk++) {
            float a[8], b[4];
            *(float4*)&a[0] = *(float4*)&Xs[kk][tr * 8];
            *(float4*)&a[4] = *(float4*)&Xs[kk][tr * 8 + 4];
            *(float4*)&b[0] = *(float4*)&Ws[kk][tc * 4];
            #pragma unroll
            for (int i = 0; i < 8; i++)
                #pragma unroll
                for (int j = 0; j < 4; j++) acc[i][j] += a[i] * b[j];
        }
        __syncthreads();
    }
    #pragma unroll
    for (int i = 0; i < 8; i++) {
        int gr = m0 + tr * 8 + i;
        if (gr < M) {
            float4 v = make_float4(acc[i][0], acc[i][1], acc[i][2], acc[i][3]);
            *(float4*)&g_h1[(size_t)gr * 64 + tc * 4] = v;
        }
    }
    // fused per-row attention logits: reduce across the 16 tc lanes
    float4 asv = *(const float4*)&att_s[tc * 4];
    float4 adv = *(const float4*)&att_d[tc * 4];
    #pragma unroll
    for (int i = 0; i < 8; i++) {
        float pas = acc[i][0] * asv.x + acc[i][1] * asv.y + acc[i][2] * asv.z + acc[i][3] * asv.w;
        float pad = acc[i][0] * adv.x + acc[i][1] * adv.y + acc[i][2] * adv.z + acc[i][3] * adv.w;
        #pragma unroll
        for (int o = 8; o; o >>= 1) {
            pas += __shfl_xor_sync(0xffffffffu, pas, o);
            pad += __shfl_xor_sync(0xffffffffu, pad, o);
        }
        if (tc == 0) {
            int gr = m0 + tr * 8 + i;
            if (gr < M) { g_as1[gr] = pas; g_ad1[gr] = pad; }
        }
    }
}

// ---------------- scatter edges into dst-sorted order, precompute w1 ----------------
__device__ __forceinline__ void sort_one(int s, int d, float a, float c1) {
    float lg = g_as1[s] + g_ad1[d] + a * c1;
    lg = lg > 0.f ? lg : 0.2f * lg;
    float w = __expf(lg);
    int pos = atomicAdd(&g_cursor[d], 1);
    g_sedge[pos] = make_int2(s, __float_as_int(w));
    g_sattr[pos] = a;
}

__global__ void sort_kernel(const int* __restrict__ ei, const float* __restrict__ ea,
                            int E, int N) {
    int t = blockIdx.x * blockDim.x + threadIdx.x;
    int eB = (E + 3) >> 2;
    int nB = (N + 3) >> 2;
    const float c1 = g_scal[0];
    if (t < eB) {
        int q = t * 4;
        if (q + 3 < E && ((E & 3) == 0)) {
            int4 s4 = *(const int4*)&ei[q];
            int4 d4 = *(const int4*)&ei[E + q];
            float4 a4 = *(const float4*)&ea[q];
            // batch the gathers for MLP
            float as0 = g_as1[s4.x], as1v = g_as1[s4.y], as2v = g_as1[s4.z], as3 = g_as1[s4.w];
            float ad0 = g_ad1[d4.x], ad1v = g_ad1[d4.y], ad2v = g_ad1[d4.z], ad3 = g_ad1[d4.w];
            float lg0 = as0 + ad0 + a4.x * c1; lg0 = lg0 > 0.f ? lg0 : 0.2f * lg0;
            float lg1 = as1v + ad1v + a4.y * c1; lg1 = lg1 > 0.f ? lg1 : 0.2f * lg1;
            float lg2 = as2v + ad2v + a4.z * c1; lg2 = lg2 > 0.f ? lg2 : 0.2f * lg2;
            float lg3 = as3 + ad3 + a4.w * c1; lg3 = lg3 > 0.f ? lg3 : 0.2f * lg3;
            float w0 = __expf(lg0), w1 = __expf(lg1), w2 = __expf(lg2), w3 = __expf(lg3);
            int p0 = atomicAdd(&g_cursor[d4.x], 1);
            int p1 = atomicAdd(&g_cursor[d4.y], 1);
            int p2 = atomicAdd(&g_cursor[d4.z], 1);
            int p3 = atomicAdd(&g_cursor[d4.w], 1);
            g_sedge[p0] = make_int2(s4.x, __float_as_int(w0)); g_sattr[p0] = a4.x;
            g_sedge[p1] = make_int2(s4.y, __float_as_int(w1)); g_sattr[p1] = a4.y;
            g_sedge[p2] = make_int2(s4.z, __float_as_int(w2)); g_sattr[p2] = a4.z;
            g_sedge[p3] = make_int2(s4.w, __float_as_int(w3)); g_sattr[p3] = a4.w;
        } else {
            for (int k = 0; k < 4 && q + k < E; k++)
                sort_one(ei[q + k], ei[E + q + k], ea[q + k], c1);
        }
    } else if (t < eB + nB) {
        int i0 = (t - eB) * 4;
        float mean = g_scal[4];
        for (int k = 0; k < 4 && i0 + k < N; k++)
            sort_one(i0 + k, i0 + k, mean, c1);
    }
}

// ---------------- layer-1 aggregation (warp/node, 4-way unroll) + fused mid ---------
__global__ void aggr1_kernel(const float* __restrict__ bias1, const float* __restrict__ W2,
                             const float* __restrict__ as2, const float* __restrict__ ad2,
                             int N) {
    int warp = (blockIdx.x * blockDim.x + threadIdx.x) >> 5;
    int lane = threadIdx.x & 31;
    if (warp >= N) return;
    const int beg = g_start[warp];
    const int end = g_start[warp + 1];
    float2 acc = make_float2(0.f, 0.f);
    float dsum = 0.f;
    int i = beg;
    for (; i + 4 <= end; i += 4) {
        int2 e0 = g_sedge[i + 0];
        int2 e1 = g_sedge[i + 1];
        int2 e2 = g_sedge[i + 2];
        int2 e3 = g_sedge[i + 3];
        float2 h0 = *(const float2*)&g_h1[(size_t)e0.x * 64 + 2 * lane];
        float2 h1v = *(const float2*)&g_h1[(size_t)e1.x * 64 + 2 * lane];
        float2 h2 = *(const float2*)&g_h1[(size_t)e2.x * 64 + 2 * lane];
        float2 h3 = *(const float2*)&g_h1[(size_t)e3.x * 64 + 2 * lane];
        float w0 = __int_as_float(e0.y), w1 = __int_as_float(e1.y);
        float w2 = __int_as_float(e2.y), w3 = __int_as_float(e3.y);
        acc.x += w0 * h0.x; acc.y += w0 * h0.y;
        acc.x += w1 * h1v.x; acc.y += w1 * h1v.y;
        acc.x += w2 * h2.x; acc.y += w2 * h2.y;
        acc.x += w3 * h3.x; acc.y += w3 * h3.y;
        dsum += (w0 + w1) + (w2 + w3);
    }
    for (; i < end; i++) {
        int2 e0 = g_sedge[i];
        float w0 = __int_as_float(e0.y);
        float2 h0 = *(const float2*)&g_h1[(size_t)e0.x * 64 + 2 * lane];
        acc.x += w0 * h0.x; acc.y += w0 * h0.y;
        dsum += w0;
    }
    float inv = 1.f / (dsum + 1e-16f);
    // fused: bias + relu + W2 projection + layer-2 logit coefficients
    float2 b = *(const float2*)&bias1[lane * 2];
    float v0 = fmaxf(acc.x * inv + b.x, 0.f);
    float v1 = fmaxf(acc.y * inv + b.y, 0.f);
    float4 w4 = *(const float4*)&W2[lane * 4];   // rows 2*lane, 2*lane+1 of [64,2]
    float s0 = v0 * w4.x + v1 * w4.z;
    float s1 = v0 * w4.y + v1 * w4.w;
    #pragma unroll
    for (int o = 16; o; o >>= 1) {
        s0 += __shfl_xor_sync(0xffffffffu, s0, o);
        s1 += __shfl_xor_sync(0xffffffffu, s1, o);
    }
    if (lane == 0) {
        g_node2[warp] = make_float4(s0, s1,
                                    s0 * as2[0] + s1 * as2[1],
                                    s0 * ad2[0] + s1 * ad2[1]);
    }
}

// ---------------- layer-2 aggregation + log_softmax (4 lanes/node, 2-way unroll) -----
__global__ void aggr2_kernel(const float* __restrict__ bias2, float* __restrict__ out, int N) {
    int t = blockIdx.x * blockDim.x + threadIdx.x;
    int node = t >> 2;
    int sub = t & 3;
    if (node >= N) return;
    const float c2 = g_scal[2];
    const float add = g_node2[node].w;
    const int beg = g_start[node];
    const int end = g_start[node + 1];
    float a0 = 0.f, a1 = 0.f, ds = 0.f;
    int i = beg + sub;
    while (i + 4 < end) {
        int sA = g_sedge[i].x;       float atA = g_sattr[i];
        int sB = g_sedge[i + 4].x;   float atB = g_sattr[i + 4];
        float4 nA = g_node2[sA];
        float4 nB = g_node2[sB];
        float lgA = nA.z + add + atA * c2; lgA = lgA > 0.f ? lgA : 0.2f * lgA;
        float lgB = nB.z + add + atB * c2; lgB = lgB > 0.f ? lgB : 0.2f * lgB;
        float wA = __expf(lgA), wB = __expf(lgB);
        a0 += wA * nA.x + wB * nB.x;
        a1 += wA * nA.y + wB * nB.y;
        ds += wA + wB;
        i += 8;
    }
    if (i < end) {
        int sA = g_sedge[i].x; float atA = g_sattr[i];
        float4 nA = g_node2[sA];
        float lgA = nA.z + add + atA * c2; lgA = lgA > 0.f ? lgA : 0.2f * lgA;
        float wA = __expf(lgA);
        a0 += wA * nA.x; a1 += wA * nA.y; ds += wA;
    }
    #pragma unroll
    for (int o = 1; o <= 2; o <<= 1) {
        a0 += __shfl_xor_sync(0xffffffffu, a0, o);
        a1 += __shfl_xor_sync(0xffffffffu, a1, o);
        ds += __shfl_xor_sync(0xffffffffu, ds, o);
    }
    if (sub == 0) {
        float inv = 1.f / (ds + 1e-16f);
        float o0 = a0 * inv + bias2[0];
        float o1 = a1 * inv + bias2[1];
        float m = fmaxf(o0, o1);
        float z = logf(expf(o0 - m) + expf(o1 - m));
        out[2 * node] = o0 - m - z;
        out[2 * node + 1] = o1 - m - z;
    }
}

// ---------------- host launcher ----------------
extern "C" void kernel_launch(void* const* d_in, const int* in_sizes, int n_in,
                              void* d_out, int out_size) {
    const float* x   = (const float*)d_in[0];
    const int*   ei  = (const int*)d_in[1];
    const float* ea  = (const float*)d_in[2];
    const float* W1  = (const float*)d_in[3];
    const float* as1 = (const float*)d_in[4];
    const float* ad1 = (const float*)d_in[5];
    const float* We1 = (const float*)d_in[6];
    const float* ae1 = (const float*)d_in[7];
    const float* b1  = (const float*)d_in[8];
    const float* W2  = (const float*)d_in[9];
    const float* as2 = (const float*)d_in[10];
    const float* ad2 = (const float*)d_in[11];
    const float* We2 = (const float*)d_in[12];
    const float* ae2 = (const float*)d_in[13];
    const float* b2  = (const float*)d_in[14];
    float* out = (float*)d_out;

    const int H   = in_sizes[4];          // 64
    const int Fin = in_sizes[3] / H;      // 128
    const int N   = in_sizes[0] / Fin;    // 100000
    const int E   = in_sizes[1] / 2;      // 1600000
    const int C   = in_sizes[10];         // 2
    const int nea = in_sizes[2];          // E * ED

    const int T = 256;
    const int eB = (E + 3) >> 2;
    const int nB = (N + 3) >> 2;

    zero_kernel<<<(N + T - 1) / T, T>>>(N);
    sum_ea_kernel<<<512, T>>>(ea, nea);
    scalars_kernel<<<1, 32>>>(We1, ae1, We2, ae2, H, C, 1.0f / (float)E);

    hist_kernel<<<(eB + nB + T - 1) / T, T>>>(ei, E, N);
    scan_kernel<<<1, 1024>>>(N);

    gemm1_kernel<<<(N + 127) / 128, 256>>>(x, W1, as1, ad1, N);

    sort_kernel<<<(eB + nB + T - 1) / T, T>>>(ei, ea, E, N);

    aggr1_kernel<<<(N * 32 + T - 1) / T, T>>>(b1, W2, as2, ad2, N);

    aggr2_kernel<<<(N * 4 + T - 1) / T, T>>>(b2, out, N);
}

// round 4
// speedup vs baseline: 1.6571x; 1.0845x over previous
#include <cuda_runtime.h>
#include <cuda_fp16.h>
#include <cstdint>

// Problem-shape upper bounds (this problem: N=100000, E=1600000, E+N=1700000)
#define MAXN 100000
#define MAXE 1700000

// ---------------- device scratch (static, allocation-free) ----------------
__device__ __half2 g_h1h[(size_t)MAXN * 32];   // layer-1 features, fp16 (64 per node)
__device__ float g_as1[MAXN];                  // per-node a_src (layer 1)
__device__ float g_ad1[MAXN];                  // per-node a_dst (layer 1)
__device__ float4 g_node2[MAXN];               // {h3_0, h3_1, a_src2, a_dst2}
__device__ int2  g_sedge[MAXE];                // dst-sorted {src, w1_bits}
__device__ float g_sattr[MAXE];                // dst-sorted raw edge attr
__device__ int   g_deg[MAXN];
__device__ int   g_start[MAXN + 1];
__device__ int   g_cursor[MAXN];
__device__ float g_sum_ea;
__device__ float g_scal[6];                    // {c1, -, c2, -, mean_ea, -}

// ---------------- zero-init ----------------
__global__ void zero_kernel(int N) {
    int i = blockIdx.x * blockDim.x + threadIdx.x;
    if (i < N) g_deg[i] = 0;
    if (i == 0) g_sum_ea = 0.f;
}

// ---------------- mean(edge_attr) reduction ----------------
__global__ void sum_ea_kernel(const float* __restrict__ ea, int n) {
    __shared__ float sdata[8];
    float s = 0.f;
    for (int i = blockIdx.x * blockDim.x + threadIdx.x; i < n; i += gridDim.x * blockDim.x)
        s += ea[i];
    #pragma unroll
    for (int o = 16; o; o >>= 1) s += __shfl_xor_sync(0xffffffffu, s, o);
    if ((threadIdx.x & 31) == 0) sdata[threadIdx.x >> 5] = s;
    __syncthreads();
    if (threadIdx.x < 8) {
        float v = sdata[threadIdx.x];
        #pragma unroll
        for (int o = 4; o; o >>= 1) v += __shfl_xor_sync(0xffu, v, o);
        if (threadIdx.x == 0) atomicAdd(&g_sum_ea, v);
    }
}

// ---------------- scalar edge constants ----------------
__global__ void scalars_kernel(const float* __restrict__ We1, const float* __restrict__ ae1,
                               const float* __restrict__ We2, const float* __restrict__ ae2,
                               int H, int C, float invE) {
    if (threadIdx.x == 0) {
        float c1 = 0.f;
        for (int k = 0; k < H; k++) c1 += We1[k] * ae1[k];
        float c2 = 0.f;
        for (int k = 0; k < C; k++) c2 += We2[k] * ae2[k];
        g_scal[0] = c1;
        g_scal[2] = c2;
        g_scal[4] = g_sum_ea * invE;   // mean edge attr (self-loop fill value)
    }
}

// ---------------- histogram of destination degrees (4 items/thread) ----------------
__global__ void hist_kernel(const int* __restrict__ ei, int E, int N) {
    int t = blockIdx.x * blockDim.x + threadIdx.x;
    int eB = (E + 3) >> 2;
    int nB = (N + 3) >> 2;
    if (t < eB) {
        int q = t * 4;
        if (q + 3 < E && ((E & 3) == 0)) {
            int4 d4 = *(const int4*)&ei[E + q];
            atomicAdd(&g_deg[d4.x], 1);
            atomicAdd(&g_deg[d4.y], 1);
            atomicAdd(&g_deg[d4.z], 1);
            atomicAdd(&g_deg[d4.w], 1);
        } else {
            for (int k = 0; k < 4 && q + k < E; k++)
                atomicAdd(&g_deg[ei[E + q + k]], 1);
        }
    } else if (t < eB + nB) {
        int i0 = (t - eB) * 4;
        for (int k = 0; k < 4 && i0 + k < N; k++)
            atomicAdd(&g_deg[i0 + k], 1);
    }
}

// ---------------- single-block exclusive scan over degrees ----------------
__global__ void __launch_bounds__(1024) scan_kernel(int N) {
    __shared__ int sh[1024];
    const int tid = threadIdx.x;
    const int chunk = (((N + 1023) / 1024) + 3) & ~3;   // multiple of 4
    const int b = tid * chunk;
    const int e = min(b + chunk, N);
    int s = 0;
    if (b < N) {
        int i = b;
        for (; i + 3 < e; i += 4) {
            int4 v = *(const int4*)&g_deg[i];
            s += v.x + v.y + v.z + v.w;
        }
        for (; i < e; i++) s += g_deg[i];
    }
    sh[tid] = s;
    __syncthreads();
    #pragma unroll
    for (int off = 1; off < 1024; off <<= 1) {
        int v = (tid >= off) ? sh[tid - off] : 0;
        __syncthreads();
        sh[tid] += v;
        __syncthreads();
    }
    if (b < N) {
        int run = (tid > 0) ? sh[tid - 1] : 0;
        int i = b;
        for (; i + 3 < e; i += 4) {
            int4 v = *(const int4*)&g_deg[i];
            int4 st = make_int4(run, run + v.x, run + v.x + v.y, run + v.x + v.y + v.z);
            *(int4*)&g_start[i] = st;
            *(int4*)&g_cursor[i] = st;
            run += v.x + v.y + v.z + v.w;
        }
        for (; i < e; i++) {
            g_start[i] = run; g_cursor[i] = run;
            run += g_deg[i];
        }
        if (e == N) g_start[N] = run;
    }
}

// ---------------- SGEMM: h1 = x[M,128] @ W1[128,64], fused a_src/a_dst, fp16 out ------
__global__ void __launch_bounds__(256) gemm1_kernel(const float* __restrict__ x,
                                                    const float* __restrict__ W,
                                                    const float* __restrict__ att_s,
                                                    const float* __restrict__ att_d, int M) {
    __shared__ float Xs[16][128];
    __shared__ float Ws[16][64];
    const int tid = threadIdx.x;
    const int tr = tid >> 4;        // 0..15 -> 8 rows each
    const int tc = tid & 15;        // 0..15 -> 4 cols each
    const int m0 = blockIdx.x * 128;
    float acc[8][4];
    #pragma unroll
    for (int i = 0; i < 8; i++)
        #pragma unroll
        for (int j = 0; j < 4; j++) acc[i][j] = 0.f;

    for (int k0 = 0; k0 < 128; k0 += 16) {
        #pragma unroll
        for (int it = 0; it < 2; it++) {
            int f = it * 256 + tid;           // 0..511
            int row = f >> 2;
            int kq = (f & 3) * 4;
            float4 v = make_float4(0.f, 0.f, 0.f, 0.f);
            int gr = m0 + row;
            if (gr < M) v = *(const float4*)&x[(size_t)gr * 128 + k0 + kq];
            Xs[kq + 0][row] = v.x; Xs[kq + 1][row] = v.y;
            Xs[kq + 2][row] = v.z; Xs[kq + 3][row] = v.w;
        }
        {
            int kk = tid >> 4;
            int c4 = (tid & 15) * 4;
            *(float4*)&Ws[kk][c4] = *(const float4*)&W[(size_t)(k0 + kk) * 64 + c4];
        }
        __syncthreads();
        #pragma unroll
        for (int kk = 0; kk < 16; kk++) {
            float a[8], b[4];
            *(float4*)&a[0] = *(float4*)&Xs[kk][tr * 8];
            *(float4*)&a[4] = *(float4*)&Xs[kk][tr * 8 + 4];
            *(float4*)&b[0] = *(float4*)&Ws[kk][tc * 4];
            #pragma unroll
            for (int i = 0; i < 8; i++)
                #pragma unroll
                for (int j = 0; j < 4; j++) acc[i][j] += a[i] * b[j];
        }
        __syncthreads();
    }
    #pragma unroll
    for (int i = 0; i < 8; i++) {
        int gr = m0 + tr * 8 + i;
        if (gr < M) {
            __half2 p0 = __floats2half2_rn(acc[i][0], acc[i][1]);
            __half2 p1 = __floats2half2_rn(acc[i][2], acc[i][3]);
            g_h1h[(size_t)gr * 32 + tc * 2]     = p0;
            g_h1h[(size_t)gr * 32 + tc * 2 + 1] = p1;
        }
    }
    // fused per-row attention logits: reduce across the 16 tc lanes
    float4 asv = *(const float4*)&att_s[tc * 4];
    float4 adv = *(const float4*)&att_d[tc * 4];
    #pragma unroll
    for (int i = 0; i < 8; i++) {
        float pas = acc[i][0] * asv.x + acc[i][1] * asv.y + acc[i][2] * asv.z + acc[i][3] * asv.w;
        float pad = acc[i][0] * adv.x + acc[i][1] * adv.y + acc[i][2] * adv.z + acc[i][3] * adv.w;
        #pragma unroll
        for (int o = 8; o; o >>= 1) {
            pas += __shfl_xor_sync(0xffffffffu, pas, o);
            pad += __shfl_xor_sync(0xffffffffu, pad, o);
        }
        if (tc == 0) {
            int gr = m0 + tr * 8 + i;
            if (gr < M) { g_as1[gr] = pas; g_ad1[gr] = pad; }
        }
    }
}

// ---------------- scatter edges into dst-sorted order, precompute w1 ----------------
__device__ __forceinline__ void sort_one(int s, int d, float a, float c1) {
    float lg = g_as1[s] + g_ad1[d] + a * c1;
    lg = lg > 0.f ? lg : 0.2f * lg;
    float w = __expf(lg);
    int pos = atomicAdd(&g_cursor[d], 1);
    g_sedge[pos] = make_int2(s, __float_as_int(w));
    g_sattr[pos] = a;
}

__global__ void sort_kernel(const int* __restrict__ ei, const float* __restrict__ ea,
                            int E, int N) {
    int t = blockIdx.x * blockDim.x + threadIdx.x;
    int eB = (E + 3) >> 2;
    int nB = (N + 3) >> 2;
    const float c1 = g_scal[0];
    if (t < eB) {
        int q = t * 4;
        if (q + 3 < E && ((E & 3) == 0)) {
            int4 s4 = *(const int4*)&ei[q];
            int4 d4 = *(const int4*)&ei[E + q];
            float4 a4 = *(const float4*)&ea[q];
            float as0 = g_as1[s4.x], as1v = g_as1[s4.y], as2v = g_as1[s4.z], as3 = g_as1[s4.w];
            float ad0 = g_ad1[d4.x], ad1v = g_ad1[d4.y], ad2v = g_ad1[d4.z], ad3 = g_ad1[d4.w];
            float lg0 = as0 + ad0 + a4.x * c1; lg0 = lg0 > 0.f ? lg0 : 0.2f * lg0;
            float lg1 = as1v + ad1v + a4.y * c1; lg1 = lg1 > 0.f ? lg1 : 0.2f * lg1;
            float lg2 = as2v + ad2v + a4.z * c1; lg2 = lg2 > 0.f ? lg2 : 0.2f * lg2;
            float lg3 = as3 + ad3 + a4.w * c1; lg3 = lg3 > 0.f ? lg3 : 0.2f * lg3;
            float w0 = __expf(lg0), w1 = __expf(lg1), w2 = __expf(lg2), w3 = __expf(lg3);
            int p0 = atomicAdd(&g_cursor[d4.x], 1);
            int p1 = atomicAdd(&g_cursor[d4.y], 1);
            int p2 = atomicAdd(&g_cursor[d4.z], 1);
            int p3 = atomicAdd(&g_cursor[d4.w], 1);
            g_sedge[p0] = make_int2(s4.x, __float_as_int(w0)); g_sattr[p0] = a4.x;
            g_sedge[p1] = make_int2(s4.y, __float_as_int(w1)); g_sattr[p1] = a4.y;
            g_sedge[p2] = make_int2(s4.z, __float_as_int(w2)); g_sattr[p2] = a4.z;
            g_sedge[p3] = make_int2(s4.w, __float_as_int(w3)); g_sattr[p3] = a4.w;
        } else {
            for (int k = 0; k < 4 && q + k < E; k++)
                sort_one(ei[q + k], ei[E + q + k], ea[q + k], c1);
        }
    } else if (t < eB + nB) {
        int i0 = (t - eB) * 4;
        float mean = g_scal[4];
        for (int k = 0; k < 4 && i0 + k < N; k++)
            sort_one(i0 + k, i0 + k, mean, c1);
    }
}

// ---------------- layer-1 aggregation (warp/node, 8-way unroll, fp16 gathers) --------
__global__ void aggr1_kernel(const float* __restrict__ bias1, const float* __restrict__ W2,
                             const float* __restrict__ as2, const float* __restrict__ ad2,
                             int N) {
    int warp = (blockIdx.x * blockDim.x + threadIdx.x) >> 5;
    int lane = threadIdx.x & 31;
    if (warp >= N) return;
    const int beg = g_start[warp];
    const int end = g_start[warp + 1];
    float2 acc = make_float2(0.f, 0.f);
    float dsum = 0.f;
    int i = beg;
    for (; i + 8 <= end; i += 8) {
        int2 e0 = g_sedge[i + 0];
        int2 e1 = g_sedge[i + 1];
        int2 e2 = g_sedge[i + 2];
        int2 e3 = g_sedge[i + 3];
        int2 e4 = g_sedge[i + 4];
        int2 e5 = g_sedge[i + 5];
        int2 e6 = g_sedge[i + 6];
        int2 e7 = g_sedge[i + 7];
        __half2 h0 = g_h1h[(size_t)e0.x * 32 + lane];
        __half2 h1v = g_h1h[(size_t)e1.x * 32 + lane];
        __half2 h2 = g_h1h[(size_t)e2.x * 32 + lane];
        __half2 h3 = g_h1h[(size_t)e3.x * 32 + lane];
        __half2 h4 = g_h1h[(size_t)e4.x * 32 + lane];
        __half2 h5 = g_h1h[(size_t)e5.x * 32 + lane];
        __half2 h6 = g_h1h[(size_t)e6.x * 32 + lane];
        __half2 h7 = g_h1h[(size_t)e7.x * 32 + lane];
        float w0 = __int_as_float(e0.y), w1 = __int_as_float(e1.y);
        float w2 = __int_as_float(e2.y), w3 = __int_as_float(e3.y);
        float w4 = __int_as_float(e4.y), w5 = __int_as_float(e5.y);
        float w6 = __int_as_float(e6.y), w7 = __int_as_float(e7.y);
        float2 f;
        f = __half22float2(h0); acc.x += w0 * f.x; acc.y += w0 * f.y;
        f = __half22float2(h1v); acc.x += w1 * f.x; acc.y += w1 * f.y;
        f = __half22float2(h2); acc.x += w2 * f.x; acc.y += w2 * f.y;
        f = __half22float2(h3); acc.x += w3 * f.x; acc.y += w3 * f.y;
        f = __half22float2(h4); acc.x += w4 * f.x; acc.y += w4 * f.y;
        f = __half22float2(h5); acc.x += w5 * f.x; acc.y += w5 * f.y;
        f = __half22float2(h6); acc.x += w6 * f.x; acc.y += w6 * f.y;
        f = __half22float2(h7); acc.x += w7 * f.x; acc.y += w7 * f.y;
        dsum += ((w0 + w1) + (w2 + w3)) + ((w4 + w5) + (w6 + w7));
    }
    for (; i < end; i++) {
        int2 e0 = g_sedge[i];
        float w0 = __int_as_float(e0.y);
        float2 f = __half22float2(g_h1h[(size_t)e0.x * 32 + lane]);
        acc.x += w0 * f.x; acc.y += w0 * f.y;
        dsum += w0;
    }
    float inv = 1.f / (dsum + 1e-16f);
    // fused: bias + relu + W2 projection + layer-2 logit coefficients
    float2 b = *(const float2*)&bias1[lane * 2];
    float v0 = fmaxf(acc.x * inv + b.x, 0.f);
    float v1 = fmaxf(acc.y * inv + b.y, 0.f);
    float4 w4v = *(const float4*)&W2[lane * 4];   // rows 2*lane, 2*lane+1 of [64,2]
    float s0 = v0 * w4v.x + v1 * w4v.z;
    float s1 = v0 * w4v.y + v1 * w4v.w;
    #pragma unroll
    for (int o = 16; o; o >>= 1) {
        s0 += __shfl_xor_sync(0xffffffffu, s0, o);
        s1 += __shfl_xor_sync(0xffffffffu, s1, o);
    }
    if (lane == 0) {
        g_node2[warp] = make_float4(s0, s1,
                                    s0 * as2[0] + s1 * as2[1],
                                    s0 * ad2[0] + s1 * ad2[1]);
    }
}

// ---------------- layer-2 aggregation + log_softmax (4 lanes/node, 2-way unroll) -----
__global__ void aggr2_kernel(const float* __restrict__ bias2, float* __restrict__ out, int N) {
    int t = blockIdx.x * blockDim.x + threadIdx.x;
    int node = t >> 2;
    int sub = t & 3;
    if (node >= N) return;
    const float c2 = g_scal[2];
    const float add = g_node2[node].w;
    const int beg = g_start[node];
    const int end = g_start[node + 1];
    float a0 = 0.f, a1 = 0.f, ds = 0.f;
    int i = beg + sub;
    while (i + 4 < end) {
        int sA = g_sedge[i].x;       float atA = g_sattr[i];
        int sB = g_sedge[i + 4].x;   float atB = g_sattr[i + 4];
        float4 nA = g_node2[sA];
        float4 nB = g_node2[sB];
        float lgA = nA.z + add + atA * c2; lgA = lgA > 0.f ? lgA : 0.2f * lgA;
        float lgB = nB.z + add + atB * c2; lgB = lgB > 0.f ? lgB : 0.2f * lgB;
        float wA = __expf(lgA), wB = __expf(lgB);
        a0 += wA * nA.x + wB * nB.x;
        a1 += wA * nA.y + wB * nB.y;
        ds += wA + wB;
        i += 8;
    }
    if (i < end) {
        int sA = g_sedge[i].x; float atA = g_sattr[i];
        float4 nA = g_node2[sA];
        float lgA = nA.z + add + atA * c2; lgA = lgA > 0.f ? lgA : 0.2f * lgA;
        float wA = __expf(lgA);
        a0 += wA * nA.x; a1 += wA * nA.y; ds += wA;
    }
    #pragma unroll
    for (int o = 1; o <= 2; o <<= 1) {
        a0 += __shfl_xor_sync(0xffffffffu, a0, o);
        a1 += __shfl_xor_sync(0xffffffffu, a1, o);
        ds += __shfl_xor_sync(0xffffffffu, ds, o);
    }
    if (sub == 0) {
        float inv = 1.f / (ds + 1e-16f);
        float o0 = a0 * inv + bias2[0];
        float o1 = a1 * inv + bias2[1];
        float m = fmaxf(o0, o1);
        float z = logf(expf(o0 - m) + expf(o1 - m));
        out[2 * node] = o0 - m - z;
        out[2 * node + 1] = o1 - m - z;
    }
}

// ---------------- host launcher ----------------
extern "C" void kernel_launch(void* const* d_in, const int* in_sizes, int n_in,
                              void* d_out, int out_size) {
    const float* x   = (const float*)d_in[0];
    const int*   ei  = (const int*)d_in[1];
    const float* ea  = (const float*)d_in[2];
    const float* W1  = (const float*)d_in[3];
    const float* as1 = (const float*)d_in[4];
    const float* ad1 = (const float*)d_in[5];
    const float* We1 = (const float*)d_in[6];
    const float* ae1 = (const float*)d_in[7];
    const float* b1  = (const float*)d_in[8];
    const float* W2  = (const float*)d_in[9];
    const float* as2 = (const float*)d_in[10];
    const float* ad2 = (const float*)d_in[11];
    const float* We2 = (const float*)d_in[12];
    const float* ae2 = (const float*)d_in[13];
    const float* b2  = (const float*)d_in[14];
    float* out = (float*)d_out;

    const int H   = in_sizes[4];          // 64
    const int Fin = in_sizes[3] / H;      // 128
    const int N   = in_sizes[0] / Fin;    // 100000
    const int E   = in_sizes[1] / 2;      // 1600000
    const int C   = in_sizes[10];         // 2
    const int nea = in_sizes[2];          // E * ED

    const int T = 256;
    const int eB = (E + 3) >> 2;
    const int nB = (N + 3) >> 2;

    // Fork the preprocessing chain onto a side stream so it overlaps the GEMM.
    cudaStream_t s_pre;
    cudaEvent_t ev_fork, ev_join;
    cudaStreamCreateWithFlags(&s_pre, cudaStreamNonBlocking);
    cudaEventCreateWithFlags(&ev_fork, cudaEventDisableTiming);
    cudaEventCreateWithFlags(&ev_join, cudaEventDisableTiming);

    cudaEventRecord(ev_fork, 0);
    cudaStreamWaitEvent(s_pre, ev_fork, 0);

    // side stream: zero -> sum_ea -> scalars -> hist -> scan
    zero_kernel<<<(N + T - 1) / T, T, 0, s_pre>>>(N);
    sum_ea_kernel<<<512, T, 0, s_pre>>>(ea, nea);
    scalars_kernel<<<1, 32, 0, s_pre>>>(We1, ae1, We2, ae2, H, C, 1.0f / (float)E);
    hist_kernel<<<(eB + nB + T - 1) / T, T, 0, s_pre>>>(ei, E, N);
    scan_kernel<<<1, 1024, 0, s_pre>>>(N);
    cudaEventRecord(ev_join, s_pre);

    // main stream: gemm runs concurrently with the chain above
    gemm1_kernel<<<(N + 127) / 128, 256>>>(x, W1, as1, ad1, N);

    cudaStreamWaitEvent((cudaStream_t)0, ev_join, 0);

    sort_kernel<<<(eB + nB + T - 1) / T, T>>>(ei, ea, E, N);
    aggr1_kernel<<<(N * 32 + T - 1) / T, T>>>(b1, W2, as2, ad2, N);
    aggr2_kernel<<<(N * 4 + T - 1) / T, T>>>(b2, out, N);

    cudaEventDestroy(ev_fork);
    cudaEventDestroy(ev_join);
    cudaStreamDestroy(s_pre);
}

// round 5
// speedup vs baseline: 1.7730x; 1.0700x over previous
#include <cuda_runtime.h>
#include <cuda_fp16.h>
#include <cstdint>

// Problem-shape upper bounds (this problem: N=100000, E=1600000, E+N=1700000)
#define MAXN 100000
#define MAXE 1700000

// ---------------- device scratch (static, allocation-free) ----------------
__device__ __half2 g_h1h[(size_t)MAXN * 32];   // layer-1 features, fp16 (64 per node)
__device__ float g_as1[MAXN];                  // per-node a_src (layer 1)
__device__ float g_ad1[MAXN];                  // per-node a_dst (layer 1)
__device__ float4 g_node2[MAXN];               // {h3_0, h3_1, a_src2, a_dst2}
__device__ int4  g_sedge[MAXE];                // dst-sorted {src, w1_bits, attr_bits, pad}
__device__ int   g_deg[MAXN];
__device__ int   g_start[MAXN + 1];
__device__ int   g_cursor[MAXN];
__device__ float g_sum_ea;
__device__ float g_scal[6];                    // {c1, -, c2, -, mean_ea, -}

// ---------------- f32x2 packed-FMA helpers (Blackwell FFMA2) ----------------
__device__ __forceinline__ unsigned long long pack2(float lo, float hi) {
    unsigned long long r;
    asm("mov.b64 %0, {%1,%2};" : "=l"(r)
        : "r"(__float_as_uint(lo)), "r"(__float_as_uint(hi)));
    return r;
}
__device__ __forceinline__ void fma2(unsigned long long& d,
                                     unsigned long long a, unsigned long long b) {
    asm("fma.rn.f32x2 %0, %1, %2, %0;" : "+l"(d) : "l"(a), "l"(b));
}
__device__ __forceinline__ float2 unpack2(unsigned long long v) {
    unsigned lo, hi;
    asm("mov.b64 {%0,%1}, %2;" : "=r"(lo), "=r"(hi) : "l"(v));
    return make_float2(__uint_as_float(lo), __uint_as_float(hi));
}

// ---------------- zero-init ----------------
__global__ void zero_kernel(int N) {
    int i = blockIdx.x * blockDim.x + threadIdx.x;
    if (i < N) g_deg[i] = 0;
    if (i == 0) g_sum_ea = 0.f;
}

// ---------------- mean(edge_attr) reduction ----------------
__global__ void sum_ea_kernel(const float* __restrict__ ea, int n) {
    __shared__ float sdata[8];
    float s = 0.f;
    for (int i = blockIdx.x * blockDim.x + threadIdx.x; i < n; i += gridDim.x * blockDim.x)
        s += ea[i];
    #pragma unroll
    for (int o = 16; o; o >>= 1) s += __shfl_xor_sync(0xffffffffu, s, o);
    if ((threadIdx.x & 31) == 0) sdata[threadIdx.x >> 5] = s;
    __syncthreads();
    if (threadIdx.x < 8) {
        float v = sdata[threadIdx.x];
        #pragma unroll
        for (int o = 4; o; o >>= 1) v += __shfl_xor_sync(0xffu, v, o);
        if (threadIdx.x == 0) atomicAdd(&g_sum_ea, v);
    }
}

// ---------------- scalar edge constants ----------------
__global__ void scalars_kernel(const float* __restrict__ We1, const float* __restrict__ ae1,
                               const float* __restrict__ We2, const float* __restrict__ ae2,
                               int H, int C, float invE) {
    if (threadIdx.x == 0) {
        float c1 = 0.f;
        for (int k = 0; k < H; k++) c1 += We1[k] * ae1[k];
        float c2 = 0.f;
        for (int k = 0; k < C; k++) c2 += We2[k] * ae2[k];
        g_scal[0] = c1;
        g_scal[2] = c2;
        g_scal[4] = g_sum_ea * invE;   // mean edge attr (self-loop fill value)
    }
}

// ---------------- histogram of destination degrees (4 items/thread) ----------------
__global__ void hist_kernel(const int* __restrict__ ei, int E, int N) {
    int t = blockIdx.x * blockDim.x + threadIdx.x;
    int eB = (E + 3) >> 2;
    int nB = (N + 3) >> 2;
    if (t < eB) {
        int q = t * 4;
        if (q + 3 < E && ((E & 3) == 0)) {
            int4 d4 = *(const int4*)&ei[E + q];
            atomicAdd(&g_deg[d4.x], 1);
            atomicAdd(&g_deg[d4.y], 1);
            atomicAdd(&g_deg[d4.z], 1);
            atomicAdd(&g_deg[d4.w], 1);
        } else {
            for (int k = 0; k < 4 && q + k < E; k++)
                atomicAdd(&g_deg[ei[E + q + k]], 1);
        }
    } else if (t < eB + nB) {
        int i0 = (t - eB) * 4;
        for (int k = 0; k < 4 && i0 + k < N; k++)
            atomicAdd(&g_deg[i0 + k], 1);
    }
}

// ---------------- single-block exclusive scan over degrees ----------------
__global__ void __launch_bounds__(1024) scan_kernel(int N) {
    __shared__ int sh[1024];
    const int tid = threadIdx.x;
    const int chunk = (((N + 1023) / 1024) + 3) & ~3;   // multiple of 4
    const int b = tid * chunk;
    const int e = min(b + chunk, N);
    int s = 0;
    if (b < N) {
        int i = b;
        for (; i + 3 < e; i += 4) {
            int4 v = *(const int4*)&g_deg[i];
            s += v.x + v.y + v.z + v.w;
        }
        for (; i < e; i++) s += g_deg[i];
    }
    sh[tid] = s;
    __syncthreads();
    #pragma unroll
    for (int off = 1; off < 1024; off <<= 1) {
        int v = (tid >= off) ? sh[tid - off] : 0;
        __syncthreads();
        sh[tid] += v;
        __syncthreads();
    }
    if (b < N) {
        int run = (tid > 0) ? sh[tid - 1] : 0;
        int i = b;
        for (; i + 3 < e; i += 4) {
            int4 v = *(const int4*)&g_deg[i];
            int4 st = make_int4(run, run + v.x, run + v.x + v.y, run + v.x + v.y + v.z);
            *(int4*)&g_start[i] = st;
            *(int4*)&g_cursor[i] = st;
            run += v.x + v.y + v.z + v.w;
        }
        for (; i < e; i++) {
            g_start[i] = run; g_cursor[i] = run;
            run += g_deg[i];
        }
        if (e == N) g_start[N] = run;
    }
}

// ---------------- SGEMM: h1 = x[M,128] @ W1[128,64], FFMA2 inner, fp16 out ------
__global__ void __launch_bounds__(256) gemm1_kernel(const float* __restrict__ x,
                                                    const float* __restrict__ W,
                                                    const float* __restrict__ att_s,
                                                    const float* __restrict__ att_d, int M) {
    __shared__ float Xs[16][128];
    __shared__ float Ws[16][64];
    const int tid = threadIdx.x;
    const int tr = tid >> 4;        // 0..15 -> 8 rows each
    const int tc = tid & 15;        // 0..15 -> 4 cols each
    const int m0 = blockIdx.x * 128;
    unsigned long long accp[8][2];
    #pragma unroll
    for (int i = 0; i < 8; i++) { accp[i][0] = 0ull; accp[i][1] = 0ull; }

    for (int k0 = 0; k0 < 128; k0 += 16) {
        #pragma unroll
        for (int it = 0; it < 2; it++) {
            int f = it * 256 + tid;           // 0..511
            int row = f >> 2;
            int kq = (f & 3) * 4;
            float4 v = make_float4(0.f, 0.f, 0.f, 0.f);
            int gr = m0 + row;
            if (gr < M) v = *(const float4*)&x[(size_t)gr * 128 + k0 + kq];
            Xs[kq + 0][row] = v.x; Xs[kq + 1][row] = v.y;
            Xs[kq + 2][row] = v.z; Xs[kq + 3][row] = v.w;
        }
        {
            int kk = tid >> 4;
            int c4 = (tid & 15) * 4;
            *(float4*)&Ws[kk][c4] = *(const float4*)&W[(size_t)(k0 + kk) * 64 + c4];
        }
        __syncthreads();
        #pragma unroll
        for (int kk = 0; kk < 16; kk++) {
            float a[8], b[4];
            *(float4*)&a[0] = *(float4*)&Xs[kk][tr * 8];
            *(float4*)&a[4] = *(float4*)&Xs[kk][tr * 8 + 4];
            *(float4*)&b[0] = *(float4*)&Ws[kk][tc * 4];
            unsigned long long bp0 = pack2(b[0], b[1]);
            unsigned long long bp1 = pack2(b[2], b[3]);
            #pragma unroll
            for (int i = 0; i < 8; i++) {
                unsigned long long ap = pack2(a[i], a[i]);
                fma2(accp[i][0], ap, bp0);
                fma2(accp[i][1], ap, bp1);
            }
        }
        __syncthreads();
    }
    float acc[8][4];
    #pragma unroll
    for (int i = 0; i < 8; i++) {
        float2 lo = unpack2(accp[i][0]);
        float2 hi = unpack2(accp[i][1]);
        acc[i][0] = lo.x; acc[i][1] = lo.y; acc[i][2] = hi.x; acc[i][3] = hi.y;
    }
    #pragma unroll
    for (int i = 0; i < 8; i++) {
        int gr = m0 + tr * 8 + i;
        if (gr < M) {
            __half2 p0 = __floats2half2_rn(acc[i][0], acc[i][1]);
            __half2 p1 = __floats2half2_rn(acc[i][2], acc[i][3]);
            g_h1h[(size_t)gr * 32 + tc * 2]     = p0;
            g_h1h[(size_t)gr * 32 + tc * 2 + 1] = p1;
        }
    }
    // fused per-row attention logits: reduce across the 16 tc lanes
    float4 asv = *(const float4*)&att_s[tc * 4];
    float4 adv = *(const float4*)&att_d[tc * 4];
    #pragma unroll
    for (int i = 0; i < 8; i++) {
        float pas = acc[i][0] * asv.x + acc[i][1] * asv.y + acc[i][2] * asv.z + acc[i][3] * asv.w;
        float pad = acc[i][0] * adv.x + acc[i][1] * adv.y + acc[i][2] * adv.z + acc[i][3] * adv.w;
        #pragma unroll
        for (int o = 8; o; o >>= 1) {
            pas += __shfl_xor_sync(0xffffffffu, pas, o);
            pad += __shfl_xor_sync(0xffffffffu, pad, o);
        }
        if (tc == 0) {
            int gr = m0 + tr * 8 + i;
            if (gr < M) { g_as1[gr] = pas; g_ad1[gr] = pad; }
        }
    }
}

// ---------------- scatter edges into dst-sorted order, precompute w1 ----------------
__device__ __forceinline__ void sort_one(int s, int d, float a, float c1) {
    float lg = g_as1[s] + g_ad1[d] + a * c1;
    lg = lg > 0.f ? lg : 0.2f * lg;
    float w = __expf(lg);
    int pos = atomicAdd(&g_cursor[d], 1);
    g_sedge[pos] = make_int4(s, __float_as_int(w), __float_as_int(a), 0);
}

__global__ void sort_kernel(const int* __restrict__ ei, const float* __restrict__ ea,
                            int E, int N) {
    int t = blockIdx.x * blockDim.x + threadIdx.x;
    int eB = (E + 3) >> 2;
    int nB = (N + 3) >> 2;
    const float c1 = g_scal[0];
    if (t < eB) {
        int q = t * 4;
        if (q + 3 < E && ((E & 3) == 0)) {
            int4 s4 = *(const int4*)&ei[q];
            int4 d4 = *(const int4*)&ei[E + q];
            float4 a4 = *(const float4*)&ea[q];
            float as0 = g_as1[s4.x], as1v = g_as1[s4.y], as2v = g_as1[s4.z], as3 = g_as1[s4.w];
            float ad0 = g_ad1[d4.x], ad1v = g_ad1[d4.y], ad2v = g_ad1[d4.z], ad3 = g_ad1[d4.w];
            float lg0 = as0 + ad0 + a4.x * c1; lg0 = lg0 > 0.f ? lg0 : 0.2f * lg0;
            float lg1 = as1v + ad1v + a4.y * c1; lg1 = lg1 > 0.f ? lg1 : 0.2f * lg1;
            float lg2 = as2v + ad2v + a4.z * c1; lg2 = lg2 > 0.f ? lg2 : 0.2f * lg2;
            float lg3 = as3 + ad3 + a4.w * c1; lg3 = lg3 > 0.f ? lg3 : 0.2f * lg3;
            float w0 = __expf(lg0), w1 = __expf(lg1), w2 = __expf(lg2), w3 = __expf(lg3);
            int p0 = atomicAdd(&g_cursor[d4.x], 1);
            int p1 = atomicAdd(&g_cursor[d4.y], 1);
            int p2 = atomicAdd(&g_cursor[d4.z], 1);
            int p3 = atomicAdd(&g_cursor[d4.w], 1);
            g_sedge[p0] = make_int4(s4.x, __float_as_int(w0), __float_as_int(a4.x), 0);
            g_sedge[p1] = make_int4(s4.y, __float_as_int(w1), __float_as_int(a4.y), 0);
            g_sedge[p2] = make_int4(s4.z, __float_as_int(w2), __float_as_int(a4.z), 0);
            g_sedge[p3] = make_int4(s4.w, __float_as_int(w3), __float_as_int(a4.w), 0);
        } else {
            for (int k = 0; k < 4 && q + k < E; k++)
                sort_one(ei[q + k], ei[E + q + k], ea[q + k], c1);
        }
    } else if (t < eB + nB) {
        int i0 = (t - eB) * 4;
        float mean = g_scal[4];
        for (int k = 0; k < 4 && i0 + k < N; k++)
            sort_one(i0 + k, i0 + k, mean, c1);
    }
}

// ---------------- layer-1 aggregation: 2 nodes/warp, 16 lanes x 4 features ----------
__global__ void aggr1_kernel(const float* __restrict__ bias1, const float* __restrict__ W2,
                             const float* __restrict__ as2, const float* __restrict__ ad2,
                             int N) {
    int gwarp = (blockIdx.x * blockDim.x + threadIdx.x) >> 5;
    int lane = threadIdx.x & 31;
    int half = lane & 15;                 // feature group: 4 features each
    int node = gwarp * 2 + (lane >> 4);
    bool valid = node < N;
    const int beg = valid ? g_start[node] : 0;
    const int end = valid ? g_start[node + 1] : 0;
    float4 acc = make_float4(0.f, 0.f, 0.f, 0.f);
    float dsum = 0.f;
    int i = beg;
    for (; i + 8 <= end; i += 8) {
        int4 e0 = g_sedge[i + 0];
        int4 e1 = g_sedge[i + 1];
        int4 e2 = g_sedge[i + 2];
        int4 e3 = g_sedge[i + 3];
        int4 e4 = g_sedge[i + 4];
        int4 e5 = g_sedge[i + 5];
        int4 e6 = g_sedge[i + 6];
        int4 e7 = g_sedge[i + 7];
        uint2 h0 = *(const uint2*)&g_h1h[(size_t)e0.x * 32 + 2 * half];
        uint2 h1v = *(const uint2*)&g_h1h[(size_t)e1.x * 32 + 2 * half];
        uint2 h2 = *(const uint2*)&g_h1h[(size_t)e2.x * 32 + 2 * half];
        uint2 h3 = *(const uint2*)&g_h1h[(size_t)e3.x * 32 + 2 * half];
        uint2 h4 = *(const uint2*)&g_h1h[(size_t)e4.x * 32 + 2 * half];
        uint2 h5 = *(const uint2*)&g_h1h[(size_t)e5.x * 32 + 2 * half];
        uint2 h6 = *(const uint2*)&g_h1h[(size_t)e6.x * 32 + 2 * half];
        uint2 h7 = *(const uint2*)&g_h1h[(size_t)e7.x * 32 + 2 * half];
        float w0 = __int_as_float(e0.y), w1 = __int_as_float(e1.y);
        float w2 = __int_as_float(e2.y), w3 = __int_as_float(e3.y);
        float w4 = __int_as_float(e4.y), w5 = __int_as_float(e5.y);
        float w6 = __int_as_float(e6.y), w7 = __int_as_float(e7.y);
        float2 fa, fb;
        #define ACC1(hh, ww) \
            fa = __half22float2(*(const __half2*)&hh.x); \
            fb = __half22float2(*(const __half2*)&hh.y); \
            acc.x += ww * fa.x; acc.y += ww * fa.y; \
            acc.z += ww * fb.x; acc.w += ww * fb.y;
        ACC1(h0, w0) ACC1(h1v, w1) ACC1(h2, w2) ACC1(h3, w3)
        ACC1(h4, w4) ACC1(h5, w5) ACC1(h6, w6) ACC1(h7, w7)
        dsum += ((w0 + w1) + (w2 + w3)) + ((w4 + w5) + (w6 + w7));
    }
    for (; i < end; i++) {
        int4 e0 = g_sedge[i];
        float w0 = __int_as_float(e0.y);
        uint2 h0 = *(const uint2*)&g_h1h[(size_t)e0.x * 32 + 2 * half];
        float2 fa, fb;
        ACC1(h0, w0)
        dsum += w0;
        #undef ACC1
    }
    float inv = 1.f / (dsum + 1e-16f);
    // fused: bias + relu + W2 projection + layer-2 logit coefficients
    float4 b = *(const float4*)&bias1[half * 4];
    float v0 = fmaxf(acc.x * inv + b.x, 0.f);
    float v1 = fmaxf(acc.y * inv + b.y, 0.f);
    float v2 = fmaxf(acc.z * inv + b.z, 0.f);
    float v3 = fmaxf(acc.w * inv + b.w, 0.f);
    float4 wa = *(const float4*)&W2[half * 8];      // rows 4h,4h+1 of [64,2]
    float4 wb = *(const float4*)&W2[half * 8 + 4];  // rows 4h+2,4h+3
    float s0 = v0 * wa.x + v1 * wa.z + v2 * wb.x + v3 * wb.z;
    float s1 = v0 * wa.y + v1 * wa.w + v2 * wb.y + v3 * wb.w;
    #pragma unroll
    for (int o = 8; o; o >>= 1) {
        s0 += __shfl_xor_sync(0xffffffffu, s0, o);
        s1 += __shfl_xor_sync(0xffffffffu, s1, o);
    }
    if (valid && half == 0) {
        g_node2[node] = make_float4(s0, s1,
                                    s0 * as2[0] + s1 * as2[1],
                                    s0 * ad2[0] + s1 * ad2[1]);
    }
}

// ---------------- layer-2 aggregation + log_softmax (4 lanes/node, 2-way unroll) -----
__global__ void aggr2_kernel(const float* __restrict__ bias2, float* __restrict__ out, int N) {
    int t = blockIdx.x * blockDim.x + threadIdx.x;
    int node = t >> 2;
    int sub = t & 3;
    if (node >= N) return;
    const float c2 = g_scal[2];
    const float add = g_node2[node].w;
    const int beg = g_start[node];
    const int end = g_start[node + 1];
    float a0 = 0.f, a1 = 0.f, ds = 0.f;
    int i = beg + sub;
    while (i + 4 < end) {
        int4 eA = g_sedge[i];
        int4 eB = g_sedge[i + 4];
        float atA = __int_as_float(eA.z);
        float atB = __int_as_float(eB.z);
        float4 nA = g_node2[eA.x];
        float4 nB = g_node2[eB.x];
        float lgA = nA.z + add + atA * c2; lgA = lgA > 0.f ? lgA : 0.2f * lgA;
        float lgB = nB.z + add + atB * c2; lgB = lgB > 0.f ? lgB : 0.2f * lgB;
        float wA = __expf(lgA), wB = __expf(lgB);
        a0 += wA * nA.x + wB * nB.x;
        a1 += wA * nA.y + wB * nB.y;
        ds += wA + wB;
        i += 8;
    }
    if (i < end) {
        int4 eA = g_sedge[i];
        float atA = __int_as_float(eA.z);
        float4 nA = g_node2[eA.x];
        float lgA = nA.z + add + atA * c2; lgA = lgA > 0.f ? lgA : 0.2f * lgA;
        float wA = __expf(lgA);
        a0 += wA * nA.x; a1 += wA * nA.y; ds += wA;
    }
    #pragma unroll
    for (int o = 1; o <= 2; o <<= 1) {
        a0 += __shfl_xor_sync(0xffffffffu, a0, o);
        a1 += __shfl_xor_sync(0xffffffffu, a1, o);
        ds += __shfl_xor_sync(0xffffffffu, ds, o);
    }
    if (sub == 0) {
        float inv = 1.f / (ds + 1e-16f);
        float o0 = a0 * inv + bias2[0];
        float o1 = a1 * inv + bias2[1];
        float m = fmaxf(o0, o1);
        float z = logf(expf(o0 - m) + expf(o1 - m));
        out[2 * node] = o0 - m - z;
        out[2 * node + 1] = o1 - m - z;
    }
}

// ---------------- host launcher ----------------
extern "C" void kernel_launch(void* const* d_in, const int* in_sizes, int n_in,
                              void* d_out, int out_size) {
    const float* x   = (const float*)d_in[0];
    const int*   ei  = (const int*)d_in[1];
    const float* ea  = (const float*)d_in[2];
    const float* W1  = (const float*)d_in[3];
    const float* as1 = (const float*)d_in[4];
    const float* ad1 = (const float*)d_in[5];
    const float* We1 = (const float*)d_in[6];
    const float* ae1 = (const float*)d_in[7];
    const float* b1  = (const float*)d_in[8];
    const float* W2  = (const float*)d_in[9];
    const float* as2 = (const float*)d_in[10];
    const float* ad2 = (const float*)d_in[11];
    const float* We2 = (const float*)d_in[12];
    const float* ae2 = (const float*)d_in[13];
    const float* b2  = (const float*)d_in[14];
    float* out = (float*)d_out;

    const int H   = in_sizes[4];          // 64
    const int Fin = in_sizes[3] / H;      // 128
    const int N   = in_sizes[0] / Fin;    // 100000
    const int E   = in_sizes[1] / 2;      // 1600000
    const int C   = in_sizes[10];         // 2
    const int nea = in_sizes[2];          // E * ED

    const int T = 256;
    const int eB = (E + 3) >> 2;
    const int nB = (N + 3) >> 2;

    // Fork the preprocessing chain onto a side stream so it overlaps the GEMM.
    cudaStream_t s_pre;
    cudaEvent_t ev_fork, ev_join;
    cudaStreamCreateWithFlags(&s_pre, cudaStreamNonBlocking);
    cudaEventCreateWithFlags(&ev_fork, cudaEventDisableTiming);
    cudaEventCreateWithFlags(&ev_join, cudaEventDisableTiming);

    cudaEventRecord(ev_fork, 0);
    cudaStreamWaitEvent(s_pre, ev_fork, 0);

    // side stream: zero -> sum_ea -> scalars -> hist -> scan
    zero_kernel<<<(N + T - 1) / T, T, 0, s_pre>>>(N);
    sum_ea_kernel<<<512, T, 0, s_pre>>>(ea, nea);
    scalars_kernel<<<1, 32, 0, s_pre>>>(We1, ae1, We2, ae2, H, C, 1.0f / (float)E);
    hist_kernel<<<(eB + nB + T - 1) / T, T, 0, s_pre>>>(ei, E, N);
    scan_kernel<<<1, 1024, 0, s_pre>>>(N);
    cudaEventRecord(ev_join, s_pre);

    // main stream: gemm runs concurrently with the chain above
    gemm1_kernel<<<(N + 127) / 128, 256>>>(x, W1, as1, ad1, N);

    cudaStreamWaitEvent((cudaStream_t)0, ev_join, 0);

    sort_kernel<<<(eB + nB + T - 1) / T, T>>>(ei, ea, E, N);
    aggr1_kernel<<<((N + 1) / 2 * 32 + T - 1) / T, T>>>(b1, W2, as2, ad2, N);
    aggr2_kernel<<<(N * 4 + T - 1) / T, T>>>(b2, out, N);

    cudaEventDestroy(ev_fork);
    cudaEventDestroy(ev_join);
    cudaStreamDestroy(s_pre);
}

// round 6
// speedup vs baseline: 1.8625x; 1.0504x over previous
#include <cuda_runtime.h>
#include <cuda_fp16.h>
#include <cstdint>

// Problem-shape upper bounds (this problem: N=100000, E=1600000, E+N=1700000)
#define MAXN 100000
#define MAXE 1700000

// ---------------- device scratch (static, allocation-free) ----------------
__device__ __half2 g_h1h[(size_t)MAXN * 32];   // layer-1 features, fp16 (64 per node)
__device__ float g_as1[MAXN];                  // per-node a_src (layer 1)
__device__ float g_ad1[MAXN];                  // per-node a_dst (layer 1)
__device__ float4 g_node2[MAXN];               // {h3_0, h3_1, a_src2, a_dst2}
__device__ int4  g_sedge[MAXE];                // dst-sorted {src, w1_bits, attr_bits, pad}
__device__ int   g_deg[MAXN];
__device__ int   g_start[MAXN + 1];
__device__ int   g_cursor[MAXN];
__device__ float g_sum_ea;
__device__ float g_scal[6];                    // {c1, -, c2, -, mean_ea, -}

// ---------------- f32x2 packed-FMA helpers (Blackwell FFMA2) ----------------
__device__ __forceinline__ unsigned long long pack2(float lo, float hi) {
    unsigned long long r;
    asm("mov.b64 %0, {%1,%2};" : "=l"(r)
        : "r"(__float_as_uint(lo)), "r"(__float_as_uint(hi)));
    return r;
}
__device__ __forceinline__ void fma2(unsigned long long& d,
                                     unsigned long long a, unsigned long long b) {
    asm("fma.rn.f32x2 %0, %1, %2, %0;" : "+l"(d) : "l"(a), "l"(b));
}
__device__ __forceinline__ float2 unpack2(unsigned long long v) {
    unsigned lo, hi;
    asm("mov.b64 {%0,%1}, %2;" : "=r"(lo), "=r"(hi) : "l"(v));
    return make_float2(__uint_as_float(lo), __uint_as_float(hi));
}

// ---------------- zero-init ----------------
__global__ void zero_kernel(int N) {
    int i = blockIdx.x * blockDim.x + threadIdx.x;
    if (i < N) g_deg[i] = 0;
    if (i == 0) g_sum_ea = 0.f;
}

// ---------------- mean(edge_attr) reduction ----------------
__global__ void sum_ea_kernel(const float* __restrict__ ea, int n) {
    __shared__ float sdata[8];
    float s = 0.f;
    for (int i = blockIdx.x * blockDim.x + threadIdx.x; i < n; i += gridDim.x * blockDim.x)
        s += ea[i];
    #pragma unroll
    for (int o = 16; o; o >>= 1) s += __shfl_xor_sync(0xffffffffu, s, o);
    if ((threadIdx.x & 31) == 0) sdata[threadIdx.x >> 5] = s;
    __syncthreads();
    if (threadIdx.x < 8) {
        float v = sdata[threadIdx.x];
        #pragma unroll
        for (int o = 4; o; o >>= 1) v += __shfl_xor_sync(0xffu, v, o);
        if (threadIdx.x == 0) atomicAdd(&g_sum_ea, v);
    }
}

// ---------------- scalar edge constants ----------------
__global__ void scalars_kernel(const float* __restrict__ We1, const float* __restrict__ ae1,
                               const float* __restrict__ We2, const float* __restrict__ ae2,
                               int H, int C, float invE) {
    if (threadIdx.x == 0) {
        float c1 = 0.f;
        for (int k = 0; k < H; k++) c1 += We1[k] * ae1[k];
        float c2 = 0.f;
        for (int k = 0; k < C; k++) c2 += We2[k] * ae2[k];
        g_scal[0] = c1;
        g_scal[2] = c2;
        g_scal[4] = g_sum_ea * invE;   // mean edge attr (self-loop fill value)
    }
}

// ---------------- histogram of destination degrees (4 items/thread) ----------------
__global__ void hist_kernel(const int* __restrict__ ei, int E, int N) {
    int t = blockIdx.x * blockDim.x + threadIdx.x;
    int eB = (E + 3) >> 2;
    int nB = (N + 3) >> 2;
    if (t < eB) {
        int q = t * 4;
        if (q + 3 < E && ((E & 3) == 0)) {
            int4 d4 = *(const int4*)&ei[E + q];
            atomicAdd(&g_deg[d4.x], 1);
            atomicAdd(&g_deg[d4.y], 1);
            atomicAdd(&g_deg[d4.z], 1);
            atomicAdd(&g_deg[d4.w], 1);
        } else {
            for (int k = 0; k < 4 && q + k < E; k++)
                atomicAdd(&g_deg[ei[E + q + k]], 1);
        }
    } else if (t < eB + nB) {
        int i0 = (t - eB) * 4;
        for (int k = 0; k < 4 && i0 + k < N; k++)
            atomicAdd(&g_deg[i0 + k], 1);
    }
}

// ---------------- single-block exclusive scan over degrees ----------------
__global__ void __launch_bounds__(1024) scan_kernel(int N) {
    __shared__ int sh[1024];
    const int tid = threadIdx.x;
    const int chunk = (((N + 1023) / 1024) + 3) & ~3;   // multiple of 4
    const int b = tid * chunk;
    const int e = min(b + chunk, N);
    int s = 0;
    if (b < N) {
        int i = b;
        for (; i + 3 < e; i += 4) {
            int4 v = *(const int4*)&g_deg[i];
            s += v.x + v.y + v.z + v.w;
        }
        for (; i < e; i++) s += g_deg[i];
    }
    sh[tid] = s;
    __syncthreads();
    #pragma unroll
    for (int off = 1; off < 1024; off <<= 1) {
        int v = (tid >= off) ? sh[tid - off] : 0;
        __syncthreads();
        sh[tid] += v;
        __syncthreads();
    }
    if (b < N) {
        int run = (tid > 0) ? sh[tid - 1] : 0;
        int i = b;
        for (; i + 3 < e; i += 4) {
            int4 v = *(const int4*)&g_deg[i];
            int4 st = make_int4(run, run + v.x, run + v.x + v.y, run + v.x + v.y + v.z);
            *(int4*)&g_start[i] = st;
            *(int4*)&g_cursor[i] = st;
            run += v.x + v.y + v.z + v.w;
        }
        for (; i < e; i++) {
            g_start[i] = run; g_cursor[i] = run;
            run += g_deg[i];
        }
        if (e == N) g_start[N] = run;
    }
}

// ---------------- SGEMM: h1 = x[M,128] @ W1[128,64] ----------------
// FFMA2 inner with M-dim pairing: a-pairs come straight from 8B LDS (no packs),
// only 4 b-duplications per k-step. fp16 output + fused attention logits.
__global__ void __launch_bounds__(256) gemm1_kernel(const float* __restrict__ x,
                                                    const float* __restrict__ W,
                                                    const float* __restrict__ att_s,
                                                    const float* __restrict__ att_d, int M) {
    __shared__ float Xs[16][128];
    __shared__ float Ws[16][64];
    const int tid = threadIdx.x;
    const int tr = tid >> 4;        // 0..15 -> 8 rows each
    const int tc = tid & 15;        // 0..15 -> 4 cols each
    const int m0 = blockIdx.x * 128;
    unsigned long long accp[4][4];  // [col j][row-pair p] -> rows 2p,2p+1
    #pragma unroll
    for (int j = 0; j < 4; j++)
        #pragma unroll
        for (int p = 0; p < 4; p++) accp[j][p] = 0ull;

    for (int k0 = 0; k0 < 128; k0 += 16) {
        #pragma unroll
        for (int it = 0; it < 2; it++) {
            int f = it * 256 + tid;           // 0..511
            int row = f >> 2;
            int kq = (f & 3) * 4;
            float4 v = make_float4(0.f, 0.f, 0.f, 0.f);
            int gr = m0 + row;
            if (gr < M) v = *(const float4*)&x[(size_t)gr * 128 + k0 + kq];
            Xs[kq + 0][row] = v.x; Xs[kq + 1][row] = v.y;
            Xs[kq + 2][row] = v.z; Xs[kq + 3][row] = v.w;
        }
        {
            int kk = tid >> 4;
            int c4 = (tid & 15) * 4;
            *(float4*)&Ws[kk][c4] = *(const float4*)&W[(size_t)(k0 + kk) * 64 + c4];
        }
        __syncthreads();
        #pragma unroll
        for (int kk = 0; kk < 16; kk++) {
            unsigned long long ap[4];
            #pragma unroll
            for (int p = 0; p < 4; p++)
                ap[p] = *(const unsigned long long*)&Xs[kk][tr * 8 + 2 * p];
            float4 bv = *(const float4*)&Ws[kk][tc * 4];
            unsigned long long bd0 = pack2(bv.x, bv.x);
            unsigned long long bd1 = pack2(bv.y, bv.y);
            unsigned long long bd2 = pack2(bv.z, bv.z);
            unsigned long long bd3 = pack2(bv.w, bv.w);
            #pragma unroll
            for (int p = 0; p < 4; p++) {
                fma2(accp[0][p], ap[p], bd0);
                fma2(accp[1][p], ap[p], bd1);
                fma2(accp[2][p], ap[p], bd2);
                fma2(accp[3][p], ap[p], bd3);
            }
        }
        __syncthreads();
    }
    float acc[8][4];
    #pragma unroll
    for (int j = 0; j < 4; j++)
        #pragma unroll
        for (int p = 0; p < 4; p++) {
            float2 pr = unpack2(accp[j][p]);
            acc[2 * p][j] = pr.x;
            acc[2 * p + 1][j] = pr.y;
        }
    #pragma unroll
    for (int i = 0; i < 8; i++) {
        int gr = m0 + tr * 8 + i;
        if (gr < M) {
            __half2 p0 = __floats2half2_rn(acc[i][0], acc[i][1]);
            __half2 p1 = __floats2half2_rn(acc[i][2], acc[i][3]);
            g_h1h[(size_t)gr * 32 + tc * 2]     = p0;
            g_h1h[(size_t)gr * 32 + tc * 2 + 1] = p1;
        }
    }
    // fused per-row attention logits: reduce across the 16 tc lanes
    float4 asv = *(const float4*)&att_s[tc * 4];
    float4 adv = *(const float4*)&att_d[tc * 4];
    #pragma unroll
    for (int i = 0; i < 8; i++) {
        float pas = acc[i][0] * asv.x + acc[i][1] * asv.y + acc[i][2] * asv.z + acc[i][3] * asv.w;
        float pad = acc[i][0] * adv.x + acc[i][1] * adv.y + acc[i][2] * adv.z + acc[i][3] * adv.w;
        #pragma unroll
        for (int o = 8; o; o >>= 1) {
            pas += __shfl_xor_sync(0xffffffffu, pas, o);
            pad += __shfl_xor_sync(0xffffffffu, pad, o);
        }
        if (tc == 0) {
            int gr = m0 + tr * 8 + i;
            if (gr < M) { g_as1[gr] = pas; g_ad1[gr] = pad; }
        }
    }
}

// ---------------- scatter edges into dst-sorted order, precompute w1 ----------------
__device__ __forceinline__ void sort_one(int s, int d, float a, float c1) {
    float lg = g_as1[s] + g_ad1[d] + a * c1;
    lg = lg > 0.f ? lg : 0.2f * lg;
    float w = __expf(lg);
    int pos = atomicAdd(&g_cursor[d], 1);
    g_sedge[pos] = make_int4(s, __float_as_int(w), __float_as_int(a), 0);
}

__global__ void sort_kernel(const int* __restrict__ ei, const float* __restrict__ ea,
                            int E, int N) {
    int t = blockIdx.x * blockDim.x + threadIdx.x;
    int eB = (E + 3) >> 2;
    int nB = (N + 3) >> 2;
    const float c1 = g_scal[0];
    if (t < eB) {
        int q = t * 4;
        if (q + 3 < E && ((E & 3) == 0)) {
            int4 s4 = *(const int4*)&ei[q];
            int4 d4 = *(const int4*)&ei[E + q];
            float4 a4 = *(const float4*)&ea[q];
            float as0 = g_as1[s4.x], as1v = g_as1[s4.y], as2v = g_as1[s4.z], as3 = g_as1[s4.w];
            float ad0 = g_ad1[d4.x], ad1v = g_ad1[d4.y], ad2v = g_ad1[d4.z], ad3 = g_ad1[d4.w];
            float lg0 = as0 + ad0 + a4.x * c1; lg0 = lg0 > 0.f ? lg0 : 0.2f * lg0;
            float lg1 = as1v + ad1v + a4.y * c1; lg1 = lg1 > 0.f ? lg1 : 0.2f * lg1;
            float lg2 = as2v + ad2v + a4.z * c1; lg2 = lg2 > 0.f ? lg2 : 0.2f * lg2;
            float lg3 = as3 + ad3 + a4.w * c1; lg3 = lg3 > 0.f ? lg3 : 0.2f * lg3;
            float w0 = __expf(lg0), w1 = __expf(lg1), w2 = __expf(lg2), w3 = __expf(lg3);
            int p0 = atomicAdd(&g_cursor[d4.x], 1);
            int p1 = atomicAdd(&g_cursor[d4.y], 1);
            int p2 = atomicAdd(&g_cursor[d4.z], 1);
            int p3 = atomicAdd(&g_cursor[d4.w], 1);
            g_sedge[p0] = make_int4(s4.x, __float_as_int(w0), __float_as_int(a4.x), 0);
            g_sedge[p1] = make_int4(s4.y, __float_as_int(w1), __float_as_int(a4.y), 0);
            g_sedge[p2] = make_int4(s4.z, __float_as_int(w2), __float_as_int(a4.z), 0);
            g_sedge[p3] = make_int4(s4.w, __float_as_int(w3), __float_as_int(a4.w), 0);
        } else {
            for (int k = 0; k < 4 && q + k < E; k++)
                sort_one(ei[q + k], ei[E + q + k], ea[q + k], c1);
        }
    } else if (t < eB + nB) {
        int i0 = (t - eB) * 4;
        float mean = g_scal[4];
        for (int k = 0; k < 4 && i0 + k < N; k++)
            sort_one(i0 + k, i0 + k, mean, c1);
    }
}

// ---------------- layer-1 aggregation: 4 nodes/warp, 8 lanes x 8 features ----------
__global__ void aggr1_kernel(const float* __restrict__ bias1, const float* __restrict__ W2,
                             const float* __restrict__ as2, const float* __restrict__ ad2,
                             int N) {
    int gwarp = (blockIdx.x * blockDim.x + threadIdx.x) >> 5;
    int lane = threadIdx.x & 31;
    int sub = lane & 7;                   // feature group: 8 features each
    int node = gwarp * 4 + (lane >> 3);
    bool valid = node < N;
    const int beg = valid ? g_start[node] : 0;
    const int end = valid ? g_start[node + 1] : 0;
    float2 a0 = make_float2(0.f, 0.f), a1 = make_float2(0.f, 0.f);
    float2 a2 = make_float2(0.f, 0.f), a3 = make_float2(0.f, 0.f);
    float dsum = 0.f;
    int i = beg;
    #define GATHER(hh, ee) uint4 hh = *(const uint4*)&g_h1h[(size_t)(ee).x * 32 + 4 * sub]
    #define ACC1(hh, ww) { \
        float2 f0 = __half22float2(*(const __half2*)&hh.x); \
        float2 f1 = __half22float2(*(const __half2*)&hh.y); \
        float2 f2 = __half22float2(*(const __half2*)&hh.z); \
        float2 f3 = __half22float2(*(const __half2*)&hh.w); \
        a0.x += ww * f0.x; a0.y += ww * f0.y; \
        a1.x += ww * f1.x; a1.y += ww * f1.y; \
        a2.x += ww * f2.x; a2.y += ww * f2.y; \
        a3.x += ww * f3.x; a3.y += ww * f3.y; }
    for (; i + 4 <= end; i += 4) {
        int4 e0 = g_sedge[i + 0];
        int4 e1 = g_sedge[i + 1];
        int4 e2 = g_sedge[i + 2];
        int4 e3 = g_sedge[i + 3];
        GATHER(h0, e0); GATHER(h1v, e1); GATHER(h2, e2); GATHER(h3, e3);
        float w0 = __int_as_float(e0.y), w1 = __int_as_float(e1.y);
        float w2 = __int_as_float(e2.y), w3 = __int_as_float(e3.y);
        ACC1(h0, w0) ACC1(h1v, w1) ACC1(h2, w2) ACC1(h3, w3)
        dsum += (w0 + w1) + (w2 + w3);
    }
    for (; i < end; i++) {
        int4 e0 = g_sedge[i];
        float w0 = __int_as_float(e0.y);
        GATHER(h0, e0);
        ACC1(h0, w0)
        dsum += w0;
    }
    #undef GATHER
    #undef ACC1
    float inv = 1.f / (dsum + 1e-16f);
    // fused: bias + relu + W2 projection + layer-2 logit coefficients
    float4 ba = *(const float4*)&bias1[sub * 8];
    float4 bb = *(const float4*)&bias1[sub * 8 + 4];
    float v0 = fmaxf(a0.x * inv + ba.x, 0.f);
    float v1 = fmaxf(a0.y * inv + ba.y, 0.f);
    float v2 = fmaxf(a1.x * inv + ba.z, 0.f);
    float v3 = fmaxf(a1.y * inv + ba.w, 0.f);
    float v4 = fmaxf(a2.x * inv + bb.x, 0.f);
    float v5 = fmaxf(a2.y * inv + bb.y, 0.f);
    float v6 = fmaxf(a3.x * inv + bb.z, 0.f);
    float v7 = fmaxf(a3.y * inv + bb.w, 0.f);
    // W2 rows sub*8 .. sub*8+7 of [64,2]
    float4 wa = *(const float4*)&W2[sub * 16];
    float4 wb = *(const float4*)&W2[sub * 16 + 4];
    float4 wc = *(const float4*)&W2[sub * 16 + 8];
    float4 wd = *(const float4*)&W2[sub * 16 + 12];
    float s0 = v0 * wa.x + v1 * wa.z + v2 * wb.x + v3 * wb.z
             + v4 * wc.x + v5 * wc.z + v6 * wd.x + v7 * wd.z;
    float s1 = v0 * wa.y + v1 * wa.w + v2 * wb.y + v3 * wb.w
             + v4 * wc.y + v5 * wc.w + v6 * wd.y + v7 * wd.w;
    #pragma unroll
    for (int o = 4; o; o >>= 1) {
        s0 += __shfl_xor_sync(0xffffffffu, s0, o);
        s1 += __shfl_xor_sync(0xffffffffu, s1, o);
    }
    if (valid && sub == 0) {
        g_node2[node] = make_float4(s0, s1,
                                    s0 * as2[0] + s1 * as2[1],
                                    s0 * ad2[0] + s1 * ad2[1]);
    }
}

// ---------------- layer-2 aggregation + log_softmax (4 lanes/node, 2-way unroll) -----
__global__ void aggr2_kernel(const float* __restrict__ bias2, float* __restrict__ out, int N) {
    int t = blockIdx.x * blockDim.x + threadIdx.x;
    int node = t >> 2;
    int sub = t & 3;
    if (node >= N) return;
    const float c2 = g_scal[2];
    const float add = g_node2[node].w;
    const int beg = g_start[node];
    const int end = g_start[node + 1];
    float a0 = 0.f, a1 = 0.f, ds = 0.f;
    int i = beg + sub;
    while (i + 4 < end) {
        int4 eA = g_sedge[i];
        int4 eB = g_sedge[i + 4];
        float atA = __int_as_float(eA.z);
        float atB = __int_as_float(eB.z);
        float4 nA = g_node2[eA.x];
        float4 nB = g_node2[eB.x];
        float lgA = nA.z + add + atA * c2; lgA = lgA > 0.f ? lgA : 0.2f * lgA;
        float lgB = nB.z + add + atB * c2; lgB = lgB > 0.f ? lgB : 0.2f * lgB;
        float wA = __expf(lgA), wB = __expf(lgB);
        a0 += wA * nA.x + wB * nB.x;
        a1 += wA * nA.y + wB * nB.y;
        ds += wA + wB;
        i += 8;
    }
    if (i < end) {
        int4 eA = g_sedge[i];
        float atA = __int_as_float(eA.z);
        float4 nA = g_node2[eA.x];
        float lgA = nA.z + add + atA * c2; lgA = lgA > 0.f ? lgA : 0.2f * lgA;
        float wA = __expf(lgA);
        a0 += wA * nA.x; a1 += wA * nA.y; ds += wA;
    }
    #pragma unroll
    for (int o = 1; o <= 2; o <<= 1) {
        a0 += __shfl_xor_sync(0xffffffffu, a0, o);
        a1 += __shfl_xor_sync(0xffffffffu, a1, o);
        ds += __shfl_xor_sync(0xffffffffu, ds, o);
    }
    if (sub == 0) {
        float inv = 1.f / (ds + 1e-16f);
        float o0 = a0 * inv + bias2[0];
        float o1 = a1 * inv + bias2[1];
        float m = fmaxf(o0, o1);
        float z = logf(expf(o0 - m) + expf(o1 - m));
        out[2 * node] = o0 - m - z;
        out[2 * node + 1] = o1 - m - z;
    }
}

// ---------------- host launcher ----------------
extern "C" void kernel_launch(void* const* d_in, const int* in_sizes, int n_in,
                              void* d_out, int out_size) {
    const float* x   = (const float*)d_in[0];
    const int*   ei  = (const int*)d_in[1];
    const float* ea  = (const float*)d_in[2];
    const float* W1  = (const float*)d_in[3];
    const float* as1 = (const float*)d_in[4];
    const float* ad1 = (const float*)d_in[5];
    const float* We1 = (const float*)d_in[6];
    const float* ae1 = (const float*)d_in[7];
    const float* b1  = (const float*)d_in[8];
    const float* W2  = (const float*)d_in[9];
    const float* as2 = (const float*)d_in[10];
    const float* ad2 = (const float*)d_in[11];
    const float* We2 = (const float*)d_in[12];
    const float* ae2 = (const float*)d_in[13];
    const float* b2  = (const float*)d_in[14];
    float* out = (float*)d_out;

    const int H   = in_sizes[4];          // 64
    const int Fin = in_sizes[3] / H;      // 128
    const int N   = in_sizes[0] / Fin;    // 100000
    const int E   = in_sizes[1] / 2;      // 1600000
    const int C   = in_sizes[10];         // 2
    const int nea = in_sizes[2];          // E * ED

    const int T = 256;
    const int eB = (E + 3) >> 2;
    const int nB = (N + 3) >> 2;

    // Fork the preprocessing chain onto a side stream so it overlaps the GEMM.
    cudaStream_t s_pre;
    cudaEvent_t ev_fork, ev_join;
    cudaStreamCreateWithFlags(&s_pre, cudaStreamNonBlocking);
    cudaEventCreateWithFlags(&ev_fork, cudaEventDisableTiming);
    cudaEventCreateWithFlags(&ev_join, cudaEventDisableTiming);

    cudaEventRecord(ev_fork, 0);
    cudaStreamWaitEvent(s_pre, ev_fork, 0);

    // side stream: zero -> sum_ea -> scalars -> hist -> scan
    zero_kernel<<<(N + T - 1) / T, T, 0, s_pre>>>(N);
    sum_ea_kernel<<<512, T, 0, s_pre>>>(ea, nea);
    scalars_kernel<<<1, 32, 0, s_pre>>>(We1, ae1, We2, ae2, H, C, 1.0f / (float)E);
    hist_kernel<<<(eB + nB + T - 1) / T, T, 0, s_pre>>>(ei, E, N);
    scan_kernel<<<1, 1024, 0, s_pre>>>(N);
    cudaEventRecord(ev_join, s_pre);

    // main stream: gemm runs concurrently with the chain above
    gemm1_kernel<<<(N + 127) / 128, 256>>>(x, W1, as1, ad1, N);

    cudaStreamWaitEvent((cudaStream_t)0, ev_join, 0);

    sort_kernel<<<(eB + nB + T - 1) / T, T>>>(ei, ea, E, N);
    aggr1_kernel<<<((N + 3) / 4 * 32 + T - 1) / T, T>>>(b1, W2, as2, ad2, N);
    aggr2_kernel<<<(N * 4 + T - 1) / T, T>>>(b2, out, N);

    cudaEventDestroy(ev_fork);
    cudaEventDestroy(ev_join);
    cudaStreamDestroy(s_pre);
}

// round 8
// speedup vs baseline: 1.9011x; 1.0208x over previous
#include <cuda_runtime.h>
#include <cuda_fp16.h>
#include <cstdint>

// Problem-shape upper bounds (this problem: N=100000, E=1600000, E+N=1700000)
#define MAXN 100000
#define MAXE 1700000

// ---------------- device scratch (static, allocation-free) ----------------
__device__ __half2 g_h1h[(size_t)MAXN * 32];   // layer-1 features, fp16 (64 per node)
__device__ float g_as1[MAXN];                  // per-node a_src (layer 1)
__device__ float g_ad1[MAXN];                  // per-node a_dst (layer 1)
__device__ float4 g_node2[MAXN];               // {h3_0, h3_1, a_src2, a_dst2}
__device__ int2  g_sedge[MAXE];                // dst-sorted {src, attr_bits}
__device__ int   g_deg[MAXN];
__device__ int   g_start[MAXN + 1];
__device__ int   g_cursor[MAXN];
__device__ float g_partial[512];               // per-block partial sums of edge_attr
__device__ float g_scal[6];                    // {c1, -, c2, -, mean_ea, -}

// ---------------- f32x2 packed-FMA helpers (Blackwell FFMA2) ----------------
__device__ __forceinline__ unsigned long long pack2(float lo, float hi) {
    unsigned long long r;
    asm("mov.b64 %0, {%1,%2};" : "=l"(r)
        : "r"(__float_as_uint(lo)), "r"(__float_as_uint(hi)));
    return r;
}
__device__ __forceinline__ void fma2(unsigned long long& d,
                                     unsigned long long a, unsigned long long b) {
    asm("fma.rn.f32x2 %0, %1, %2, %0;" : "+l"(d) : "l"(a), "l"(b));
}
__device__ __forceinline__ float2 unpack2(unsigned long long v) {
    unsigned lo, hi;
    asm("mov.b64 {%0,%1}, %2;" : "=r"(lo), "=r"(hi) : "l"(v));
    return make_float2(__uint_as_float(lo), __uint_as_float(hi));
}

// ---------------- pre: zero degree counters + per-block partial sums of ea -----------
// grid MUST be 512 x 256 (g_partial sized for 512 blocks)
__global__ void pre_kernel(const float* __restrict__ ea, int n, int N) {
    int t = blockIdx.x * blockDim.x + threadIdx.x;
    for (int i = t; i < N; i += 512 * 256) g_deg[i] = 0;
    float s = 0.f;
    for (int i = t; i < n; i += 512 * 256) s += ea[i];
    #pragma unroll
    for (int o = 16; o; o >>= 1) s += __shfl_xor_sync(0xffffffffu, s, o);
    __shared__ float sdata[8];
    if ((threadIdx.x & 31) == 0) sdata[threadIdx.x >> 5] = s;
    __syncthreads();
    if (threadIdx.x < 8) {
        float v = sdata[threadIdx.x];
        #pragma unroll
        for (int o = 4; o; o >>= 1) v += __shfl_xor_sync(0xffu, v, o);
        if (threadIdx.x == 0) g_partial[blockIdx.x] = v;
    }
}

// ---------------- histogram of destination degrees (4 items/thread) ----------------
__global__ void hist_kernel(const int* __restrict__ ei, int E, int N) {
    int t = blockIdx.x * blockDim.x + threadIdx.x;
    int eB = (E + 3) >> 2;
    int nB = (N + 3) >> 2;
    if (t < eB) {
        int q = t * 4;
        if (q + 3 < E && ((E & 3) == 0)) {
            int4 d4 = *(const int4*)&ei[E + q];
            atomicAdd(&g_deg[d4.x], 1);
            atomicAdd(&g_deg[d4.y], 1);
            atomicAdd(&g_deg[d4.z], 1);
            atomicAdd(&g_deg[d4.w], 1);
        } else {
            for (int k = 0; k < 4 && q + k < E; k++)
                atomicAdd(&g_deg[ei[E + q + k]], 1);
        }
    } else if (t < eB + nB) {
        int i0 = (t - eB) * 4;
        for (int k = 0; k < 4 && i0 + k < N; k++)
            atomicAdd(&g_deg[i0 + k], 1);
    }
}

// ---------------- single-block: finish ea-mean + scalars, then exclusive scan --------
__global__ void __launch_bounds__(1024) scan_kernel(const float* __restrict__ We1,
                                                    const float* __restrict__ ae1,
                                                    const float* __restrict__ We2,
                                                    const float* __restrict__ ae2,
                                                    int H, int C, float invE, int N) {
    __shared__ int sh[1024];
    __shared__ float sf[16];
    const int tid = threadIdx.x;
    // ---- part 1: reduce g_partial[512] and compute scalar constants ----
    if (tid < 512) {
        float v = g_partial[tid];
        #pragma unroll
        for (int o = 16; o; o >>= 1) v += __shfl_xor_sync(0xffffffffu, v, o);
        if ((tid & 31) == 0) sf[tid >> 5] = v;
    }
    __syncthreads();
    if (tid == 0) {
        float tot = 0.f;
        #pragma unroll
        for (int k = 0; k < 16; k++) tot += sf[k];
        float c1 = 0.f;
        for (int k = 0; k < H; k++) c1 += We1[k] * ae1[k];
        float c2 = 0.f;
        for (int k = 0; k < C; k++) c2 += We2[k] * ae2[k];
        g_scal[0] = c1;
        g_scal[2] = c2;
        g_scal[4] = tot * invE;   // mean edge attr (self-loop fill value)
    }
    __syncthreads();
    // ---- part 2: exclusive scan over degrees ----
    const int chunk = (((N + 1023) / 1024) + 3) & ~3;   // multiple of 4
    const int b = tid * chunk;
    const int e = min(b + chunk, N);
    int s = 0;
    if (b < N) {
        int i = b;
        for (; i + 3 < e; i += 4) {
            int4 v = *(const int4*)&g_deg[i];
            s += v.x + v.y + v.z + v.w;
        }
        for (; i < e; i++) s += g_deg[i];
    }
    sh[tid] = s;
    __syncthreads();
    #pragma unroll
    for (int off = 1; off < 1024; off <<= 1) {
        int v = (tid >= off) ? sh[tid - off] : 0;
        __syncthreads();
        sh[tid] += v;
        __syncthreads();
    }
    if (b < N) {
        int run = (tid > 0) ? sh[tid - 1] : 0;
        int i = b;
        for (; i + 3 < e; i += 4) {
            int4 v = *(const int4*)&g_deg[i];
            int4 st = make_int4(run, run + v.x, run + v.x + v.y, run + v.x + v.y + v.z);
            *(int4*)&g_start[i] = st;
            *(int4*)&g_cursor[i] = st;
            run += v.x + v.y + v.z + v.w;
        }
        for (; i < e; i++) {
            g_start[i] = run; g_cursor[i] = run;
            run += g_deg[i];
        }
        if (e == N) g_start[N] = run;
    }
}

// ---------------- scatter edges into dst-sorted order ({src, attr} only) -------------
__global__ void sort_kernel(const int* __restrict__ ei, const float* __restrict__ ea,
                            int E, int N) {
    int t = blockIdx.x * blockDim.x + threadIdx.x;
    int eB = (E + 3) >> 2;
    int nB = (N + 3) >> 2;
    if (t < eB) {
        int q = t * 4;
        if (q + 3 < E && ((E & 3) == 0)) {
            int4 s4 = *(const int4*)&ei[q];
            int4 d4 = *(const int4*)&ei[E + q];
            float4 a4 = *(const float4*)&ea[q];
            int p0 = atomicAdd(&g_cursor[d4.x], 1);
            int p1 = atomicAdd(&g_cursor[d4.y], 1);
            int p2 = atomicAdd(&g_cursor[d4.z], 1);
            int p3 = atomicAdd(&g_cursor[d4.w], 1);
            g_sedge[p0] = make_int2(s4.x, __float_as_int(a4.x));
            g_sedge[p1] = make_int2(s4.y, __float_as_int(a4.y));
            g_sedge[p2] = make_int2(s4.z, __float_as_int(a4.z));
            g_sedge[p3] = make_int2(s4.w, __float_as_int(a4.w));
        } else {
            for (int k = 0; k < 4 && q + k < E; k++) {
                int d = ei[E + q + k];
                int pos = atomicAdd(&g_cursor[d], 1);
                g_sedge[pos] = make_int2(ei[q + k], __float_as_int(ea[q + k]));
            }
        }
    } else if (t < eB + nB) {
        int i0 = (t - eB) * 4;
        float mean = g_scal[4];
        for (int k = 0; k < 4 && i0 + k < N; k++) {
            int d = i0 + k;
            int pos = atomicAdd(&g_cursor[d], 1);
            g_sedge[pos] = make_int2(d, __float_as_int(mean));
        }
    }
}

// ---------------- SGEMM: h1 = x[M,128] @ W1[128,64] ----------------
// FFMA2 inner with M-dim pairing; fp16 output + fused attention logits.
__global__ void __launch_bounds__(256) gemm1_kernel(const float* __restrict__ x,
                                                    const float* __restrict__ W,
                                                    const float* __restrict__ att_s,
                                                    const float* __restrict__ att_d, int M) {
    __shared__ float Xs[16][128];
    __shared__ float Ws[16][64];
    const int tid = threadIdx.x;
    const int tr = tid >> 4;        // 0..15 -> 8 rows each
    const int tc = tid & 15;        // 0..15 -> 4 cols each
    const int m0 = blockIdx.x * 128;
    unsigned long long accp[4][4];  // [col j][row-pair p] -> rows 2p,2p+1
    #pragma unroll
    for (int j = 0; j < 4; j++)
        #pragma unroll
        for (int p = 0; p < 4; p++) accp[j][p] = 0ull;

    for (int k0 = 0; k0 < 128; k0 += 16) {
        #pragma unroll
        for (int it = 0; it < 2; it++) {
            int f = it * 256 + tid;           // 0..511
            int row = f >> 2;
            int kq = (f & 3) * 4;
            float4 v = make_float4(0.f, 0.f, 0.f, 0.f);
            int gr = m0 + row;
            if (gr < M) v = *(const float4*)&x[(size_t)gr * 128 + k0 + kq];
            Xs[kq + 0][row] = v.x; Xs[kq + 1][row] = v.y;
            Xs[kq + 2][row] = v.z; Xs[kq + 3][row] = v.w;
        }
        {
            int kk = tid >> 4;
            int c4 = (tid & 15) * 4;
            *(float4*)&Ws[kk][c4] = *(const float4*)&W[(size_t)(k0 + kk) * 64 + c4];
        }
        __syncthreads();
        #pragma unroll
        for (int kk = 0; kk < 16; kk++) {
            unsigned long long ap[4];
            #pragma unroll
            for (int p = 0; p < 4; p++)
                ap[p] = *(const unsigned long long*)&Xs[kk][tr * 8 + 2 * p];
            float4 bv = *(const float4*)&Ws[kk][tc * 4];
            unsigned long long bd0 = pack2(bv.x, bv.x);
            unsigned long long bd1 = pack2(bv.y, bv.y);
            unsigned long long bd2 = pack2(bv.z, bv.z);
            unsigned long long bd3 = pack2(bv.w, bv.w);
            #pragma unroll
            for (int p = 0; p < 4; p++) {
                fma2(accp[0][p], ap[p], bd0);
                fma2(accp[1][p], ap[p], bd1);
                fma2(accp[2][p], ap[p], bd2);
                fma2(accp[3][p], ap[p], bd3);
            }
        }
        __syncthreads();
    }
    float acc[8][4];
    #pragma unroll
    for (int j = 0; j < 4; j++)
        #pragma unroll
        for (int p = 0; p < 4; p++) {
            float2 pr = unpack2(accp[j][p]);
            acc[2 * p][j] = pr.x;
            acc[2 * p + 1][j] = pr.y;
        }
    #pragma unroll
    for (int i = 0; i < 8; i++) {
        int gr = m0 + tr * 8 + i;
        if (gr < M) {
            __half2 p0 = __floats2half2_rn(acc[i][0], acc[i][1]);
            __half2 p1 = __floats2half2_rn(acc[i][2], acc[i][3]);
            g_h1h[(size_t)gr * 32 + tc * 2]     = p0;
            g_h1h[(size_t)gr * 32 + tc * 2 + 1] = p1;
        }
    }
    // fused per-row attention logits: reduce across the 16 tc lanes
    float4 asv = *(const float4*)&att_s[tc * 4];
    float4 adv = *(const float4*)&att_d[tc * 4];
    #pragma unroll
    for (int i = 0; i < 8; i++) {
        float pas = acc[i][0] * asv.x + acc[i][1] * asv.y + acc[i][2] * asv.z + acc[i][3] * asv.w;
        float pad = acc[i][0] * adv.x + acc[i][1] * adv.y + acc[i][2] * adv.z + acc[i][3] * adv.w;
        #pragma unroll
        for (int o = 8; o; o >>= 1) {
            pas += __shfl_xor_sync(0xffffffffu, pas, o);
            pad += __shfl_xor_sync(0xffffffffu, pad, o);
        }
        if (tc == 0) {
            int gr = m0 + tr * 8 + i;
            if (gr < M) { g_as1[gr] = pas; g_ad1[gr] = pad; }
        }
    }
}

// ---------------- layer-1 aggregation: 4 nodes/warp, 8 lanes x 8 features -----------
// w computed inline by lanes g<4 of each 8-lane group, broadcast with the GROUP mask
// (0xFF << group*8): all lanes named in the mask share the node, hence the same trip
// count, so the intra-loop collective is convergent (round-7 bug: full-warp mask).
__global__ void aggr1_kernel(const float* __restrict__ bias1, const float* __restrict__ W2,
                             const float* __restrict__ as2, const float* __restrict__ ad2,
                             int N) {
    int gwarp = (blockIdx.x * blockDim.x + threadIdx.x) >> 5;
    int lane = threadIdx.x & 31;
    int g = lane & 7;                     // position within the 8-lane node group
    int node = gwarp * 4 + (lane >> 3);
    bool valid = node < N;
    const unsigned gmask = 0xFFu << (lane & 24);   // this group's 8 lanes
    const float c1 = g_scal[0];
    const int beg = valid ? g_start[node] : 0;
    const int end = valid ? g_start[node + 1] : 0;
    const float add = valid ? g_ad1[node] : 0.f;
    float2 a0 = make_float2(0.f, 0.f), a1 = make_float2(0.f, 0.f);
    float2 a2 = make_float2(0.f, 0.f), a3 = make_float2(0.f, 0.f);
    float dsum = 0.f;
    int i = beg;
    #define ACC1(hh, ww) { \
        float2 f0 = __half22float2(*(const __half2*)&hh.x); \
        float2 f1 = __half22float2(*(const __half2*)&hh.y); \
        float2 f2 = __half22float2(*(const __half2*)&hh.z); \
        float2 f3 = __half22float2(*(const __half2*)&hh.w); \
        a0.x += ww * f0.x; a0.y += ww * f0.y; \
        a1.x += ww * f1.x; a1.y += ww * f1.y; \
        a2.x += ww * f2.x; a2.y += ww * f2.y; \
        a3.x += ww * f3.x; a3.y += ww * f3.y; }
    for (; i + 4 <= end; i += 4) {
        int2 e0 = g_sedge[i + 0];
        int2 e1 = g_sedge[i + 1];
        int2 e2 = g_sedge[i + 2];
        int2 e3 = g_sedge[i + 3];
        // lane g (g<4) computes w for edge i+g, broadcast within the 8-lane group
        int sel = g & 3;
        int src_o = sel == 0 ? e0.x : sel == 1 ? e1.x : sel == 2 ? e2.x : e3.x;
        int at_o  = sel == 0 ? e0.y : sel == 1 ? e1.y : sel == 2 ? e2.y : e3.y;
        float w_o = 0.f;
        if (g < 4) {
            float lg = g_as1[src_o] + add + __int_as_float(at_o) * c1;
            lg = lg > 0.f ? lg : 0.2f * lg;
            w_o = __expf(lg);
        }
        float w0 = __shfl_sync(gmask, w_o, 0, 8);
        float w1 = __shfl_sync(gmask, w_o, 1, 8);
        float w2 = __shfl_sync(gmask, w_o, 2, 8);
        float w3 = __shfl_sync(gmask, w_o, 3, 8);
        uint4 h0 = *(const uint4*)&g_h1h[(size_t)e0.x * 32 + 4 * g];
        uint4 h1v = *(const uint4*)&g_h1h[(size_t)e1.x * 32 + 4 * g];
        uint4 h2 = *(const uint4*)&g_h1h[(size_t)e2.x * 32 + 4 * g];
        uint4 h3 = *(const uint4*)&g_h1h[(size_t)e3.x * 32 + 4 * g];
        ACC1(h0, w0) ACC1(h1v, w1) ACC1(h2, w2) ACC1(h3, w3)
        dsum += (w0 + w1) + (w2 + w3);
    }
    for (; i < end; i++) {
        int2 e0 = g_sedge[i];
        float w_o = 0.f;
        if (g == 0) {
            float lg = g_as1[e0.x] + add + __int_as_float(e0.y) * c1;
            lg = lg > 0.f ? lg : 0.2f * lg;
            w_o = __expf(lg);
        }
        float w0 = __shfl_sync(gmask, w_o, 0, 8);
        uint4 h0 = *(const uint4*)&g_h1h[(size_t)e0.x * 32 + 4 * g];
        ACC1(h0, w0)
        dsum += w0;
    }
    #undef ACC1
    float inv = 1.f / (dsum + 1e-16f);
    // fused: bias + relu + W2 projection + layer-2 logit coefficients
    float4 ba = *(const float4*)&bias1[g * 8];
    float4 bb = *(const float4*)&bias1[g * 8 + 4];
    float v0 = fmaxf(a0.x * inv + ba.x, 0.f);
    float v1 = fmaxf(a0.y * inv + ba.y, 0.f);
    float v2 = fmaxf(a1.x * inv + ba.z, 0.f);
    float v3 = fmaxf(a1.y * inv + ba.w, 0.f);
    float v4 = fmaxf(a2.x * inv + bb.x, 0.f);
    float v5 = fmaxf(a2.y * inv + bb.y, 0.f);
    float v6 = fmaxf(a3.x * inv + bb.z, 0.f);
    float v7 = fmaxf(a3.y * inv + bb.w, 0.f);
    // W2 rows g*8 .. g*8+7 of [64,2]
    float4 wa = *(const float4*)&W2[g * 16];
    float4 wb = *(const float4*)&W2[g * 16 + 4];
    float4 wc = *(const float4*)&W2[g * 16 + 8];
    float4 wd = *(const float4*)&W2[g * 16 + 12];
    float s0 = v0 * wa.x + v1 * wa.z + v2 * wb.x + v3 * wb.z
             + v4 * wc.x + v5 * wc.z + v6 * wd.x + v7 * wd.z;
    float s1 = v0 * wa.y + v1 * wa.w + v2 * wb.y + v3 * wb.w
             + v4 * wc.y + v5 * wc.w + v6 * wd.y + v7 * wd.w;
    // all 32 lanes reach here (no early return) -> full-warp-safe xor reduce within groups
    #pragma unroll
    for (int o = 4; o; o >>= 1) {
        s0 += __shfl_xor_sync(0xffffffffu, s0, o);
        s1 += __shfl_xor_sync(0xffffffffu, s1, o);
    }
    if (valid && g == 0) {
        g_node2[node] = make_float4(s0, s1,
                                    s0 * as2[0] + s1 * as2[1],
                                    s0 * ad2[0] + s1 * ad2[1]);
    }
}

// ---------------- layer-2 aggregation + log_softmax (4 lanes/node, 2-way unroll) -----
__global__ void aggr2_kernel(const float* __restrict__ bias2, float* __restrict__ out, int N) {
    int t = blockIdx.x * blockDim.x + threadIdx.x;
    int node = t >> 2;
    int sub = t & 3;
    bool valid = node < N;
    const float c2 = g_scal[2];
    const float add = valid ? g_node2[node].w : 0.f;
    const int beg = valid ? g_start[node] : 0;
    const int end = valid ? g_start[node + 1] : 0;
    float a0 = 0.f, a1 = 0.f, ds = 0.f;
    int i = beg + sub;
    while (i + 4 < end) {
        int2 eA = g_sedge[i];
        int2 eB = g_sedge[i + 4];
        float atA = __int_as_float(eA.y);
        float atB = __int_as_float(eB.y);
        float4 nA = g_node2[eA.x];
        float4 nB = g_node2[eB.x];
        float lgA = nA.z + add + atA * c2; lgA = lgA > 0.f ? lgA : 0.2f * lgA;
        float lgB = nB.z + add + atB * c2; lgB = lgB > 0.f ? lgB : 0.2f * lgB;
        float wA = __expf(lgA), wB = __expf(lgB);
        a0 += wA * nA.x + wB * nB.x;
        a1 += wA * nA.y + wB * nB.y;
        ds += wA + wB;
        i += 8;
    }
    if (i < end) {
        int2 eA = g_sedge[i];
        float atA = __int_as_float(eA.y);
        float4 nA = g_node2[eA.x];
        float lgA = nA.z + add + atA * c2; lgA = lgA > 0.f ? lgA : 0.2f * lgA;
        float wA = __expf(lgA);
        a0 += wA * nA.x; a1 += wA * nA.y; ds += wA;
    }
    #pragma unroll
    for (int o = 1; o <= 2; o <<= 1) {
        a0 += __shfl_xor_sync(0xffffffffu, a0, o);
        a1 += __shfl_xor_sync(0xffffffffu, a1, o);
        ds += __shfl_xor_sync(0xffffffffu, ds, o);
    }
    if (valid && sub == 0) {
        float inv = 1.f / (ds + 1e-16f);
        float o0 = a0 * inv + bias2[0];
        float o1 = a1 * inv + bias2[1];
        float m = fmaxf(o0, o1);
        float z = logf(expf(o0 - m) + expf(o1 - m));
        out[2 * node] = o0 - m - z;
        out[2 * node + 1] = o1 - m - z;
    }
}

// ---------------- host launcher ----------------
extern "C" void kernel_launch(void* const* d_in, const int* in_sizes, int n_in,
                              void* d_out, int out_size) {
    const float* x   = (const float*)d_in[0];
    const int*   ei  = (const int*)d_in[1];
    const float* ea  = (const float*)d_in[2];
    const float* W1  = (const float*)d_in[3];
    const float* as1 = (const float*)d_in[4];
    const float* ad1 = (const float*)d_in[5];
    const float* We1 = (const float*)d_in[6];
    const float* ae1 = (const float*)d_in[7];
    const float* b1  = (const float*)d_in[8];
    const float* W2  = (const float*)d_in[9];
    const float* as2 = (const float*)d_in[10];
    const float* ad2 = (const float*)d_in[11];
    const float* We2 = (const float*)d_in[12];
    const float* ae2 = (const float*)d_in[13];
    const float* b2  = (const float*)d_in[14];
    float* out = (float*)d_out;

    const int H   = in_sizes[4];          // 64
    const int Fin = in_sizes[3] / H;      // 128
    const int N   = in_sizes[0] / Fin;    // 100000
    const int E   = in_sizes[1] / 2;      // 1600000
    const int C   = in_sizes[10];         // 2
    const int nea = in_sizes[2];          // E * ED

    const int T = 256;
    const int eB = (E + 3) >> 2;
    const int nB = (N + 3) >> 2;

    // Fork: the ENTIRE preprocessing + CSR-sort pipeline is independent of the
    // GEMM (w computed inside aggr1), so it all overlaps on a side stream.
    cudaStream_t s_pre;
    cudaEvent_t ev_fork, ev_join;
    cudaStreamCreateWithFlags(&s_pre, cudaStreamNonBlocking);
    cudaEventCreateWithFlags(&ev_fork, cudaEventDisableTiming);
    cudaEventCreateWithFlags(&ev_join, cudaEventDisableTiming);

    cudaEventRecord(ev_fork, 0);
    cudaStreamWaitEvent(s_pre, ev_fork, 0);

    // side stream: pre -> hist -> scan(+scalars) -> sort
    pre_kernel<<<512, T, 0, s_pre>>>(ea, nea, N);
    hist_kernel<<<(eB + nB + T - 1) / T, T, 0, s_pre>>>(ei, E, N);
    scan_kernel<<<1, 1024, 0, s_pre>>>(We1, ae1, We2, ae2, H, C, 1.0f / (float)E, N);
    sort_kernel<<<(eB + nB + T - 1) / T, T, 0, s_pre>>>(ei, ea, E, N);
    cudaEventRecord(ev_join, s_pre);

    // main stream: gemm runs concurrently with the whole chain above
    gemm1_kernel<<<(N + 127) / 128, 256>>>(x, W1, as1, ad1, N);

    cudaStreamWaitEvent((cudaStream_t)0, ev_join, 0);

    aggr1_kernel<<<((N + 3) / 4 * 32 + T - 1) / T, T>>>(b1, W2, as2, ad2, N);
    aggr2_kernel<<<(N * 4 + T - 1) / T, T>>>(b2, out, N);

    cudaEventDestroy(ev_fork);
    cudaEventDestroy(ev_join);
    cudaStreamDestroy(s_pre);
}

// round 9
// speedup vs baseline: 1.9438x; 1.0225x over previous
#include <cuda_runtime.h>
#include <cuda_fp16.h>
#include <cstdint>

// Problem-shape upper bounds (this problem: N=100000, E=1600000, E+N=1700000)
#define MAXN 100000
#define MAXE 1700000

// ---------------- device scratch (static, allocation-free) ----------------
__device__ __half2 g_h1h[(size_t)MAXN * 32];   // layer-1 features, fp16 (64 per node)
__device__ float g_as1[MAXN];                  // per-node a_src (layer 1)
__device__ float g_ad1[MAXN];                  // per-node a_dst (layer 1)
__device__ float4 g_node2[MAXN];               // {h3_0, h3_1, a_src2, a_dst2}
__device__ int2  g_sedge[MAXE];                // dst-sorted {src, attr_bits}
__device__ int   g_deg[MAXN];
__device__ int   g_start[MAXN + 1];
__device__ int   g_cursor[MAXN];
__device__ float g_partial[512];               // per-block partial sums of edge_attr
__device__ float g_scal[6];                    // {c1, -, c2, -, mean_ea, -}

// ---------------- f32x2 packed-FMA helpers (Blackwell FFMA2) ----------------
__device__ __forceinline__ unsigned long long pack2(float lo, float hi) {
    unsigned long long r;
    asm("mov.b64 %0, {%1,%2};" : "=l"(r)
        : "r"(__float_as_uint(lo)), "r"(__float_as_uint(hi)));
    return r;
}
__device__ __forceinline__ void fma2(unsigned long long& d,
                                     unsigned long long a, unsigned long long b) {
    asm("fma.rn.f32x2 %0, %1, %2, %0;" : "+l"(d) : "l"(a), "l"(b));
}
__device__ __forceinline__ float2 unpack2(unsigned long long v) {
    unsigned lo, hi;
    asm("mov.b64 {%0,%1}, %2;" : "=r"(lo), "=r"(hi) : "l"(v));
    return make_float2(__uint_as_float(lo), __uint_as_float(hi));
}

// ---------------- fused: partial sums of edge_attr + dst-degree histogram ------------
// grid MUST be 512 x 256 (g_partial sized for 512 blocks); g_deg pre-zeroed by memset.
__global__ void prehist_kernel(const float* __restrict__ ea, int nea,
                               const int* __restrict__ ei, int E) {
    const int t = blockIdx.x * blockDim.x + threadIdx.x;
    const int stride = 512 * 256;
    float s = 0.f;
    for (int i = t; i < nea; i += stride) s += ea[i];
    #pragma unroll
    for (int o = 16; o; o >>= 1) s += __shfl_xor_sync(0xffffffffu, s, o);
    __shared__ float sdata[8];
    if ((threadIdx.x & 31) == 0) sdata[threadIdx.x >> 5] = s;
    __syncthreads();
    if (threadIdx.x < 8) {
        float v = sdata[threadIdx.x];
        #pragma unroll
        for (int o = 4; o; o >>= 1) v += __shfl_xor_sync(0xffu, v, o);
        if (threadIdx.x == 0) g_partial[blockIdx.x] = v;
    }
    // histogram of destinations (edges only; self-loops handled via deg+1 in scan)
    const int e4 = E >> 2;
    for (int i = t; i < e4; i += stride) {
        int4 d4 = *(const int4*)&ei[E + i * 4];
        atomicAdd(&g_deg[d4.x], 1);
        atomicAdd(&g_deg[d4.y], 1);
        atomicAdd(&g_deg[d4.z], 1);
        atomicAdd(&g_deg[d4.w], 1);
    }
    if (t < (E & 3)) atomicAdd(&g_deg[ei[E + e4 * 4 + t]], 1);
}

// ---------------- single-block: ea-mean + scalars, exclusive scan over (deg+1) -------
// Reserves slot start[i] for node i's self-loop: cursor starts at start[i]+1.
__global__ void __launch_bounds__(1024) scan_kernel(const float* __restrict__ We1,
                                                    const float* __restrict__ ae1,
                                                    const float* __restrict__ We2,
                                                    const float* __restrict__ ae2,
                                                    int H, int C, float invE, int N) {
    __shared__ int sh[1024];
    __shared__ float sf[16];
    const int tid = threadIdx.x;
    if (tid < 512) {
        float v = g_partial[tid];
        #pragma unroll
        for (int o = 16; o; o >>= 1) v += __shfl_xor_sync(0xffffffffu, v, o);
        if ((tid & 31) == 0) sf[tid >> 5] = v;
    }
    __syncthreads();
    if (tid == 0) {
        float tot = 0.f;
        #pragma unroll
        for (int k = 0; k < 16; k++) tot += sf[k];
        float c1 = 0.f;
        for (int k = 0; k < H; k++) c1 += We1[k] * ae1[k];
        float c2 = 0.f;
        for (int k = 0; k < C; k++) c2 += We2[k] * ae2[k];
        g_scal[0] = c1;
        g_scal[2] = c2;
        g_scal[4] = tot * invE;   // mean edge attr (self-loop fill value)
    }
    __syncthreads();
    const int chunk = (((N + 1023) / 1024) + 3) & ~3;   // multiple of 4
    const int b = tid * chunk;
    const int e = min(b + chunk, N);
    int s = 0;
    if (b < N) {
        int i = b;
        for (; i + 3 < e; i += 4) {
            int4 v = *(const int4*)&g_deg[i];
            s += v.x + v.y + v.z + v.w + 4;
        }
        for (; i < e; i++) s += g_deg[i] + 1;
    }
    sh[tid] = s;
    __syncthreads();
    #pragma unroll
    for (int off = 1; off < 1024; off <<= 1) {
        int v = (tid >= off) ? sh[tid - off] : 0;
        __syncthreads();
        sh[tid] += v;
        __syncthreads();
    }
    if (b < N) {
        int run = (tid > 0) ? sh[tid - 1] : 0;
        int i = b;
        for (; i + 3 < e; i += 4) {
            int4 v = *(const int4*)&g_deg[i];
            int4 st = make_int4(run,
                                run + v.x + 1,
                                run + v.x + v.y + 2,
                                run + v.x + v.y + v.z + 3);
            *(int4*)&g_start[i] = st;
            int4 cu = make_int4(st.x + 1, st.y + 1, st.z + 1, st.w + 1);
            *(int4*)&g_cursor[i] = cu;
            run += v.x + v.y + v.z + v.w + 4;
        }
        for (; i < e; i++) {
            g_start[i] = run; g_cursor[i] = run + 1;
            run += g_deg[i] + 1;
        }
        if (e == N) g_start[N] = run;
    }
}

// ---------------- scatter edges into dst-sorted order (8 edges/thread) ---------------
// Self-loops go into the reserved slot start[i] with a PLAIN store (no atomic).
__global__ void sort_kernel(const int* __restrict__ ei, const float* __restrict__ ea,
                            int E, int N) {
    int t = blockIdx.x * blockDim.x + threadIdx.x;
    int eB = (E + 7) >> 3;
    int nB = (N + 3) >> 2;
    if (t < eB) {
        int q = t * 8;
        if (q + 7 < E && ((E & 7) == 0)) {
            int4 sa = *(const int4*)&ei[q];
            int4 sb = *(const int4*)&ei[q + 4];
            int4 da = *(const int4*)&ei[E + q];
            int4 db = *(const int4*)&ei[E + q + 4];
            float4 aa = *(const float4*)&ea[q];
            float4 ab = *(const float4*)&ea[q + 4];
            int p0 = atomicAdd(&g_cursor[da.x], 1);
            int p1 = atomicAdd(&g_cursor[da.y], 1);
            int p2 = atomicAdd(&g_cursor[da.z], 1);
            int p3 = atomicAdd(&g_cursor[da.w], 1);
            int p4 = atomicAdd(&g_cursor[db.x], 1);
            int p5 = atomicAdd(&g_cursor[db.y], 1);
            int p6 = atomicAdd(&g_cursor[db.z], 1);
            int p7 = atomicAdd(&g_cursor[db.w], 1);
            g_sedge[p0] = make_int2(sa.x, __float_as_int(aa.x));
            g_sedge[p1] = make_int2(sa.y, __float_as_int(aa.y));
            g_sedge[p2] = make_int2(sa.z, __float_as_int(aa.z));
            g_sedge[p3] = make_int2(sa.w, __float_as_int(aa.w));
            g_sedge[p4] = make_int2(sb.x, __float_as_int(ab.x));
            g_sedge[p5] = make_int2(sb.y, __float_as_int(ab.y));
            g_sedge[p6] = make_int2(sb.z, __float_as_int(ab.z));
            g_sedge[p7] = make_int2(sb.w, __float_as_int(ab.w));
        } else {
            for (int k = 0; k < 8 && q + k < E; k++) {
                int d = ei[E + q + k];
                int pos = atomicAdd(&g_cursor[d], 1);
                g_sedge[pos] = make_int2(ei[q + k], __float_as_int(ea[q + k]));
            }
        }
    } else if (t < eB + nB) {
        int i0 = (t - eB) * 4;
        float mean = g_scal[4];
        int4 st = *(const int4*)&g_start[i0 & ~3];   // i0 is 4-aligned by construction
        int sarr[4] = {st.x, st.y, st.z, st.w};
        for (int k = 0; k < 4 && i0 + k < N; k++)
            g_sedge[sarr[k]] = make_int2(i0 + k, __float_as_int(mean));
    }
}

// ---------------- SGEMM: h1 = x[M,128] @ W1[128,64] ----------------
// FFMA2 inner with M-dim pairing; fp16 output + fused attention logits.
__global__ void __launch_bounds__(256) gemm1_kernel(const float* __restrict__ x,
                                                    const float* __restrict__ W,
                                                    const float* __restrict__ att_s,
                                                    const float* __restrict__ att_d, int M) {
    __shared__ float Xs[16][128];
    __shared__ float Ws[16][64];
    const int tid = threadIdx.x;
    const int tr = tid >> 4;        // 0..15 -> 8 rows each
    const int tc = tid & 15;        // 0..15 -> 4 cols each
    const int m0 = blockIdx.x * 128;
    unsigned long long accp[4][4];  // [col j][row-pair p] -> rows 2p,2p+1
    #pragma unroll
    for (int j = 0; j < 4; j++)
        #pragma unroll
        for (int p = 0; p < 4; p++) accp[j][p] = 0ull;

    for (int k0 = 0; k0 < 128; k0 += 16) {
        #pragma unroll
        for (int it = 0; it < 2; it++) {
            int f = it * 256 + tid;           // 0..511
            int row = f >> 2;
            int kq = (f & 3) * 4;
            float4 v = make_float4(0.f, 0.f, 0.f, 0.f);
            int gr = m0 + row;
            if (gr < M) v = *(const float4*)&x[(size_t)gr * 128 + k0 + kq];
            Xs[kq + 0][row] = v.x; Xs[kq + 1][row] = v.y;
            Xs[kq + 2][row] = v.z; Xs[kq + 3][row] = v.w;
        }
        {
            int kk = tid >> 4;
            int c4 = (tid & 15) * 4;
            *(float4*)&Ws[kk][c4] = *(const float4*)&W[(size_t)(k0 + kk) * 64 + c4];
        }
        __syncthreads();
        #pragma unroll
        for (int kk = 0; kk < 16; kk++) {
            unsigned long long ap[4];
            #pragma unroll
            for (int p = 0; p < 4; p++)
                ap[p] = *(const unsigned long long*)&Xs[kk][tr * 8 + 2 * p];
            float4 bv = *(const float4*)&Ws[kk][tc * 4];
            unsigned long long bd0 = pack2(bv.x, bv.x);
            unsigned long long bd1 = pack2(bv.y, bv.y);
            unsigned long long bd2 = pack2(bv.z, bv.z);
            unsigned long long bd3 = pack2(bv.w, bv.w);
            #pragma unroll
            for (int p = 0; p < 4; p++) {
                fma2(accp[0][p], ap[p], bd0);
                fma2(accp[1][p], ap[p], bd1);
                fma2(accp[2][p], ap[p], bd2);
                fma2(accp[3][p], ap[p], bd3);
            }
        }
        __syncthreads();
    }
    float acc[8][4];
    #pragma unroll
    for (int j = 0; j < 4; j++)
        #pragma unroll
        for (int p = 0; p < 4; p++) {
            float2 pr = unpack2(accp[j][p]);
            acc[2 * p][j] = pr.x;
            acc[2 * p + 1][j] = pr.y;
        }
    #pragma unroll
    for (int i = 0; i < 8; i++) {
        int gr = m0 + tr * 8 + i;
        if (gr < M) {
            __half2 p0 = __floats2half2_rn(acc[i][0], acc[i][1]);
            __half2 p1 = __floats2half2_rn(acc[i][2], acc[i][3]);
            g_h1h[(size_t)gr * 32 + tc * 2]     = p0;
            g_h1h[(size_t)gr * 32 + tc * 2 + 1] = p1;
        }
    }
    // fused per-row attention logits: reduce across the 16 tc lanes
    float4 asv = *(const float4*)&att_s[tc * 4];
    float4 adv = *(const float4*)&att_d[tc * 4];
    #pragma unroll
    for (int i = 0; i < 8; i++) {
        float pas = acc[i][0] * asv.x + acc[i][1] * asv.y + acc[i][2] * asv.z + acc[i][3] * asv.w;
        float pad = acc[i][0] * adv.x + acc[i][1] * adv.y + acc[i][2] * adv.z + acc[i][3] * adv.w;
        #pragma unroll
        for (int o = 8; o; o >>= 1) {
            pas += __shfl_xor_sync(0xffffffffu, pas, o);
            pad += __shfl_xor_sync(0xffffffffu, pad, o);
        }
        if (tc == 0) {
            int gr = m0 + tr * 8 + i;
            if (gr < M) { g_as1[gr] = pas; g_ad1[gr] = pad; }
        }
    }
}

// ---------------- layer-1 aggregation: 4 nodes/warp, 8-edge unroll -------------------
// Each lane loads its own sedge entry (coalesced 64B per group) and computes its own
// w (no idle lanes); {src, w} circulate via width-8 shuffles with the GROUP mask.
__global__ void aggr1_kernel(const float* __restrict__ bias1, const float* __restrict__ W2,
                             const float* __restrict__ as2, const float* __restrict__ ad2,
                             int N) {
    int gwarp = (blockIdx.x * blockDim.x + threadIdx.x) >> 5;
    int lane = threadIdx.x & 31;
    int g = lane & 7;                     // position within the 8-lane node group
    int node = gwarp * 4 + (lane >> 3);
    bool valid = node < N;
    const unsigned gmask = 0xFFu << (lane & 24);   // this group's 8 lanes
    const float c1 = g_scal[0];
    const int beg = valid ? g_start[node] : 0;
    const int end = valid ? g_start[node + 1] : 0;
    const float add = valid ? g_ad1[node] : 0.f;
    float2 a0 = make_float2(0.f, 0.f), a1 = make_float2(0.f, 0.f);
    float2 a2 = make_float2(0.f, 0.f), a3 = make_float2(0.f, 0.f);
    float dsum = 0.f;
    int i = beg;
    #define ACC1(hh, ww) { \
        float2 f0 = __half22float2(*(const __half2*)&hh.x); \
        float2 f1 = __half22float2(*(const __half2*)&hh.y); \
        float2 f2 = __half22float2(*(const __half2*)&hh.z); \
        float2 f3 = __half22float2(*(const __half2*)&hh.w); \
        a0.x += ww * f0.x; a0.y += ww * f0.y; \
        a1.x += ww * f1.x; a1.y += ww * f1.y; \
        a2.x += ww * f2.x; a2.y += ww * f2.y; \
        a3.x += ww * f3.x; a3.y += ww * f3.y; }
    for (; i + 8 <= end; i += 8) {
        int2 eg = g_sedge[i + g];          // coalesced: 8 lanes cover 64B
        float lg = g_as1[eg.x] + add + __int_as_float(eg.y) * c1;
        lg = lg > 0.f ? lg : 0.2f * lg;
        float wg = __expf(lg);
        #pragma unroll
        for (int j = 0; j < 8; j++) {
            int   sj = __shfl_sync(gmask, eg.x, j, 8);
            float wj = __shfl_sync(gmask, wg, j, 8);
            uint4 h = *(const uint4*)&g_h1h[(size_t)sj * 32 + 4 * g];
            ACC1(h, wj)
            dsum += wj;
        }
    }
    {
        int rem = end - i;
        if (rem > 0) {
            int2 eg = (g < rem) ? g_sedge[i + g] : make_int2(0, 0);
            float wg = 0.f;
            if (g < rem) {
                float lg = g_as1[eg.x] + add + __int_as_float(eg.y) * c1;
                lg = lg > 0.f ? lg : 0.2f * lg;
                wg = __expf(lg);
            }
            for (int j = 0; j < rem; j++) {
                int   sj = __shfl_sync(gmask, eg.x, j, 8);
                float wj = __shfl_sync(gmask, wg, j, 8);
                uint4 h = *(const uint4*)&g_h1h[(size_t)sj * 32 + 4 * g];
                ACC1(h, wj)
                dsum += wj;
            }
        }
    }
    #undef ACC1
    float inv = 1.f / (dsum + 1e-16f);
    // fused: bias + relu + W2 projection + layer-2 logit coefficients
    float4 ba = *(const float4*)&bias1[g * 8];
    float4 bb = *(const float4*)&bias1[g * 8 + 4];
    float v0 = fmaxf(a0.x * inv + ba.x, 0.f);
    float v1 = fmaxf(a0.y * inv + ba.y, 0.f);
    float v2 = fmaxf(a1.x * inv + ba.z, 0.f);
    float v3 = fmaxf(a1.y * inv + ba.w, 0.f);
    float v4 = fmaxf(a2.x * inv + bb.x, 0.f);
    float v5 = fmaxf(a2.y * inv + bb.y, 0.f);
    float v6 = fmaxf(a3.x * inv + bb.z, 0.f);
    float v7 = fmaxf(a3.y * inv + bb.w, 0.f);
    // W2 rows g*8 .. g*8+7 of [64,2]
    float4 wa = *(const float4*)&W2[g * 16];
    float4 wb = *(const float4*)&W2[g * 16 + 4];
    float4 wc = *(const float4*)&W2[g * 16 + 8];
    float4 wd = *(const float4*)&W2[g * 16 + 12];
    float s0 = v0 * wa.x + v1 * wa.z + v2 * wb.x + v3 * wb.z
             + v4 * wc.x + v5 * wc.z + v6 * wd.x + v7 * wd.z;
    float s1 = v0 * wa.y + v1 * wa.w + v2 * wb.y + v3 * wb.w
             + v4 * wc.y + v5 * wc.w + v6 * wd.y + v7 * wd.w;
    // all 32 lanes reach here (no early return) -> full-warp-safe xor reduce within groups
    #pragma unroll
    for (int o = 4; o; o >>= 1) {
        s0 += __shfl_xor_sync(0xffffffffu, s0, o);
        s1 += __shfl_xor_sync(0xffffffffu, s1, o);
    }
    if (valid && g == 0) {
        g_node2[node] = make_float4(s0, s1,
                                    s0 * as2[0] + s1 * as2[1],
                                    s0 * ad2[0] + s1 * ad2[1]);
    }
}

// ---------------- layer-2 aggregation + log_softmax (4 lanes/node, 2-way unroll) -----
__global__ void aggr2_kernel(const float* __restrict__ bias2, float* __restrict__ out, int N) {
    int t = blockIdx.x * blockDim.x + threadIdx.x;
    int node = t >> 2;
    int sub = t & 3;
    bool valid = node < N;
    const float c2 = g_scal[2];
    const float add = valid ? g_node2[node].w : 0.f;
    const int beg = valid ? g_start[node] : 0;
    const int end = valid ? g_start[node + 1] : 0;
    float a0 = 0.f, a1 = 0.f, ds = 0.f;
    int i = beg + sub;
    while (i + 4 < end) {
        int2 eA = g_sedge[i];
        int2 eB = g_sedge[i + 4];
        float atA = __int_as_float(eA.y);
        float atB = __int_as_float(eB.y);
        float4 nA = g_node2[eA.x];
        float4 nB = g_node2[eB.x];
        float lgA = nA.z + add + atA * c2; lgA = lgA > 0.f ? lgA : 0.2f * lgA;
        float lgB = nB.z + add + atB * c2; lgB = lgB > 0.f ? lgB : 0.2f * lgB;
        float wA = __expf(lgA), wB = __expf(lgB);
        a0 += wA * nA.x + wB * nB.x;
        a1 += wA * nA.y + wB * nB.y;
        ds += wA + wB;
        i += 8;
    }
    if (i < end) {
        int2 eA = g_sedge[i];
        float atA = __int_as_float(eA.y);
        float4 nA = g_node2[eA.x];
        float lgA = nA.z + add + atA * c2; lgA = lgA > 0.f ? lgA : 0.2f * lgA;
        float wA = __expf(lgA);
        a0 += wA * nA.x; a1 += wA * nA.y; ds += wA;
    }
    #pragma unroll
    for (int o = 1; o <= 2; o <<= 1) {
        a0 += __shfl_xor_sync(0xffffffffu, a0, o);
        a1 += __shfl_xor_sync(0xffffffffu, a1, o);
        ds += __shfl_xor_sync(0xffffffffu, ds, o);
    }
    if (valid && sub == 0) {
        float inv = 1.f / (ds + 1e-16f);
        float o0 = a0 * inv + bias2[0];
        float o1 = a1 * inv + bias2[1];
        float m = fmaxf(o0, o1);
        float z = logf(expf(o0 - m) + expf(o1 - m));
        out[2 * node] = o0 - m - z;
        out[2 * node + 1] = o1 - m - z;
    }
}

// ---------------- host launcher ----------------
extern "C" void kernel_launch(void* const* d_in, const int* in_sizes, int n_in,
                              void* d_out, int out_size) {
    const float* x   = (const float*)d_in[0];
    const int*   ei  = (const int*)d_in[1];
    const float* ea  = (const float*)d_in[2];
    const float* W1  = (const float*)d_in[3];
    const float* as1 = (const float*)d_in[4];
    const float* ad1 = (const float*)d_in[5];
    const float* We1 = (const float*)d_in[6];
    const float* ae1 = (const float*)d_in[7];
    const float* b1  = (const float*)d_in[8];
    const float* W2  = (const float*)d_in[9];
    const float* as2 = (const float*)d_in[10];
    const float* ad2 = (const float*)d_in[11];
    const float* We2 = (const float*)d_in[12];
    const float* ae2 = (const float*)d_in[13];
    const float* b2  = (const float*)d_in[14];
    float* out = (float*)d_out;

    const int H   = in_sizes[4];          // 64
    const int Fin = in_sizes[3] / H;      // 128
    const int N   = in_sizes[0] / Fin;    // 100000
    const int E   = in_sizes[1] / 2;      // 1600000
    const int C   = in_sizes[10];         // 2
    const int nea = in_sizes[2];          // E * ED

    const int T = 256;
    const int eB = (E + 7) >> 3;
    const int nB = (N + 3) >> 2;

    void* deg_ptr = nullptr;
    cudaGetSymbolAddress(&deg_ptr, g_deg);

    // Fork: the ENTIRE preprocessing + CSR-sort pipeline is independent of the
    // GEMM (w computed inside aggr1), so it all overlaps on a side stream.
    cudaStream_t s_pre;
    cudaEvent_t ev_fork, ev_join;
    cudaStreamCreateWithFlags(&s_pre, cudaStreamNonBlocking);
    cudaEventCreateWithFlags(&ev_fork, cudaEventDisableTiming);
    cudaEventCreateWithFlags(&ev_join, cudaEventDisableTiming);

    cudaEventRecord(ev_fork, 0);
    cudaStreamWaitEvent(s_pre, ev_fork, 0);

    // side stream: memset(deg) -> prehist -> scan(+scalars) -> sort
    cudaMemsetAsync(deg_ptr, 0, (size_t)N * sizeof(int), s_pre);
    prehist_kernel<<<512, T, 0, s_pre>>>(ea, nea, ei, E);
    scan_kernel<<<1, 1024, 0, s_pre>>>(We1, ae1, We2, ae2, H, C, 1.0f / (float)E, N);
    sort_kernel<<<(eB + nB + T - 1) / T, T, 0, s_pre>>>(ei, ea, E, N);
    cudaEventRecord(ev_join, s_pre);

    // main stream: gemm runs concurrently with the whole chain above
    gemm1_kernel<<<(N + 127) / 128, 256>>>(x, W1, as1, ad1, N);

    cudaStreamWaitEvent((cudaStream_t)0, ev_join, 0);

    aggr1_kernel<<<((N + 3) / 4 * 32 + T - 1) / T, T>>>(b1, W2, as2, ad2, N);
    aggr2_kernel<<<(N * 4 + T - 1) / T, T>>>(b2, out, N);

    cudaEventDestroy(ev_fork);
    cudaEventDestroy(ev_join);
    cudaStreamDestroy(s_pre);
}